// round 14
// baseline (speedup 1.0000x reference)
#include <cuda_runtime.h>
#include <cuda_bf16.h>
#include <cuda_fp16.h>
#include <math.h>
#include <stdint.h>

// ---------------- problem sizes ----------------
#define L_SEQ  2048
#define BATCH  2
#define DM     768
#define DI     1536
#define DS     16
#define M_ROWS (BATCH * L_SEQ)   // 4096
#define N_XZ   (2 * DI)          // 3072
#define N_COMB 1664              // 1536 + 32, padded to 13*128
#define CCH    32                // scan chunks
#define CL     64                // chunk length

// ---------------- scratch globals ----------------
__device__ __align__(128) float g_xz[M_ROWS * N_XZ];
__device__ __align__(128) float g_dx[M_ROWS * N_COMB];

__device__ __align__(128) __half g_xh [M_ROWS * DM],  g_xl [M_ROWS * DM];
__device__ __align__(128) __half g_wi16[N_XZ * DM];
__device__ __align__(128) __half g_wc16[N_COMB * DI];
__device__ __align__(128) __half g_xch[M_ROWS * DI],  g_xcl[M_ROWS * DI];
__device__ __align__(128) __half g_y16 [M_ROWS * DI];
__device__ __align__(128) __half g_wo16[DM * DI];

__device__ __align__(128) float g_cdec[BATCH * CCH * DS * DI];
__device__ __align__(128) float g_hend[BATCH * CCH * DS * DI];
__device__ __align__(128) float g_h0  [BATCH * CCH * DS * DI];

// ---------------- PTX helpers (plain sm_80+ PTX; NO tcgen05) --------
__device__ __forceinline__ uint32_t smem_u32(const void* p) {
    uint32_t a;
    asm("{ .reg .u64 t; cvta.to.shared.u64 t, %1; cvt.u32.u64 %0, t; }" : "=r"(a) : "l"(p));
    return a;
}
#define CP_ASYNC16(dst, src) \
    asm volatile("cp.async.cg.shared.global [%0], [%1], 16;" :: "r"(dst), "l"(src))
#define CP_COMMIT() asm volatile("cp.async.commit_group;")
#define CP_WAIT(n)  asm volatile("cp.async.wait_group %0;" :: "n"(n))
#define LDSM4(r, a) \
    asm volatile("ldmatrix.sync.aligned.m8n8.x4.shared.b16 {%0,%1,%2,%3}, [%4];" \
                 : "=r"((r)[0]), "=r"((r)[1]), "=r"((r)[2]), "=r"((r)[3]) : "r"(a))
#define MMA_FP16(c, a, b0, b1) \
    asm volatile("mma.sync.aligned.m16n8k16.row.col.f32.f16.f16.f32 " \
                 "{%0,%1,%2,%3}, {%4,%5,%6,%7}, {%8,%9}, {%0,%1,%2,%3};" \
                 : "+f"((c)[0]), "+f"((c)[1]), "+f"((c)[2]), "+f"((c)[3]) \
                 : "r"((a)[0]), "r"((a)[1]), "r"((a)[2]), "r"((a)[3]), \
                   "r"(b0), "r"(b1))

// ---------------- templated fp16 GEMM: C = (Ah[+Al]) B^T ------------------
// 128x128 tile, BK=32, 80B rows, 2-stage cp.async, 2 CTA/SM.
#define F2_TILE  10240            // 128 rows * 80 bytes
#define F2_STAGE 30720            // Ah, Al, B
#define F2_SMEM  (2 * F2_STAGE)   // 61440

template<bool TWO>
__global__ __launch_bounds__(256, 2)
void gemm_f16t(const __half* __restrict__ Ah, const __half* __restrict__ Al,
               const __half* __restrict__ B, float* __restrict__ C,
               int M, int N, int K, int col0) {
    extern __shared__ __align__(128) char smem[];
    const uint32_t sb = smem_u32(smem);
    const int tid  = threadIdx.x;
    const int lane = tid & 31;
    const int wid  = tid >> 5;
    const int wm   = wid & 3;
    const int wn   = wid >> 2;
    const int bm   = blockIdx.y * 128;
    const int bn   = col0 + blockIdx.x * 128;

    const __half* srcs[3] = { Ah + (size_t)bm * K, Al + (size_t)bm * K,
                              B + (size_t)bn * K };

    auto load_stage = [&](uint32_t stb, int k0) {
#pragma unroll
        for (int i = 0; i < 6; i++) {
            const int c = i * 256 + tid;
            const int t = c >> 9, w = c & 511, r = w >> 2, j = w & 3;
            if (!TWO && t == 1) continue;      // compile-time eliminated
            CP_ASYNC16(stb + t * F2_TILE + r * 80 + j * 16,
                       srcs[t] + (size_t)r * K + k0 + j * 8);
        }
        CP_COMMIT();
    };

    float acc[2][8][4];
#pragma unroll
    for (int mt = 0; mt < 2; mt++)
#pragma unroll
        for (int nt = 0; nt < 8; nt++)
#pragma unroll
            for (int q = 0; q < 4; q++) acc[mt][nt][q] = 0.f;

    const uint32_t a_off = (uint32_t)((lane & 15) * 80 + (lane >> 4) * 16);
    const uint32_t b_off = (uint32_t)((((lane >> 4) << 3) + (lane & 7)) * 80 +
                                      ((lane >> 3) & 1) * 16);

    const int NC = K >> 5;
    load_stage(sb, 0);

    for (int it = 0; it < NC; it++) {
        if (it + 1 < NC) {
            load_stage(sb + ((it + 1) & 1) * F2_STAGE, (it + 1) << 5);
            CP_WAIT(1);
        } else {
            CP_WAIT(0);
        }
        __syncthreads();

        const uint32_t st  = sb + (it & 1) * F2_STAGE;
        const uint32_t aHb = st + wm * 32 * 80 + a_off;
        const uint32_t aLb = st + F2_TILE + wm * 32 * 80 + a_off;
        const uint32_t bBb = st + 2 * F2_TILE + wn * 64 * 80 + b_off;

#pragma unroll
        for (int kk = 0; kk < 2; kk++) {
            const uint32_t ko = kk * 32;
            uint32_t ah[2][4], bb[4][4];
#pragma unroll
            for (int mt = 0; mt < 2; mt++)
                LDSM4(ah[mt], aHb + mt * 16 * 80 + ko);
#pragma unroll
            for (int bt = 0; bt < 4; bt++)
                LDSM4(bb[bt], bBb + bt * 16 * 80 + ko);
#pragma unroll
            for (int mt = 0; mt < 2; mt++)
#pragma unroll
                for (int nt = 0; nt < 8; nt++) {
                    const int bt = nt >> 1, hh = (nt & 1) << 1;
                    MMA_FP16(acc[mt][nt], ah[mt], bb[bt][hh], bb[bt][hh + 1]);
                }
            if (TWO) {
                uint32_t al[2][4];
#pragma unroll
                for (int mt = 0; mt < 2; mt++)
                    LDSM4(al[mt], aLb + mt * 16 * 80 + ko);
#pragma unroll
                for (int mt = 0; mt < 2; mt++)
#pragma unroll
                    for (int nt = 0; nt < 8; nt++) {
                        const int bt = nt >> 1, hh = (nt & 1) << 1;
                        MMA_FP16(acc[mt][nt], al[mt], bb[bt][hh], bb[bt][hh + 1]);
                    }
            }
        }
        __syncthreads();
    }

    const int r0 = bm + wm * 32 + (lane >> 2);
    const int c0 = bn + wn * 64 + (lane & 3) * 2;
#pragma unroll
    for (int mt = 0; mt < 2; mt++)
#pragma unroll
        for (int nt = 0; nt < 8; nt++) {
            float* p0 = C + (size_t)(r0 + mt * 16) * N + c0 + nt * 8;
            *(float2*)p0                   = make_float2(acc[mt][nt][0], acc[mt][nt][1]);
            *(float2*)(p0 + (size_t)8 * N) = make_float2(acc[mt][nt][2], acc[mt][nt][3]);
        }
}

// ---------------- fp16 single-term GEMM (final projection) ----------------
#define T3_TILE_A 5120
#define T3_STAGE  15360
#define T3_SMEM   (2 * T3_STAGE)

__global__ __launch_bounds__(256, 3)
void gemm_fp16(const __half* __restrict__ A, const __half* __restrict__ B,
               float* __restrict__ C, int M, int N, int K) {
    extern __shared__ __align__(128) char smem[];
    const uint32_t sb = smem_u32(smem);
    const int tid = threadIdx.x, lane = tid & 31, wid = tid >> 5;
    const int wm = wid & 1, wn = wid >> 1;
    const int bm = blockIdx.y * 64, bn = blockIdx.x * 128;

    const __half* srcA = A + (size_t)bm * K;
    const __half* srcB = B + (size_t)bn * K;

    float acc[2][4][4];
#pragma unroll
    for (int mt = 0; mt < 2; mt++)
#pragma unroll
        for (int nt = 0; nt < 4; nt++)
#pragma unroll
            for (int q = 0; q < 4; q++) acc[mt][nt][q] = 0.f;

    const uint32_t a_off = (uint32_t)((lane & 15) * 80 + (lane >> 4) * 16);
    const uint32_t b_off = (uint32_t)((((lane >> 4) << 3) + (lane & 7)) * 80 +
                                      ((lane >> 3) & 1) * 16);
    const int NC = K >> 5;

    auto load_stage = [&](uint32_t stb, int k0) {
#pragma unroll
        for (int i = 0; i < 3; i++) {
            int c = i * 256 + tid;
            if (c < 256) {
                int r = c >> 2, j = c & 3;
                CP_ASYNC16(stb + r * 80 + j * 16, srcA + (size_t)r * K + k0 + j * 8);
            } else {
                int c2 = c - 256, r = c2 >> 2, j = c2 & 3;
                CP_ASYNC16(stb + T3_TILE_A + r * 80 + j * 16,
                           srcB + (size_t)r * K + k0 + j * 8);
            }
        }
        CP_COMMIT();
    };

    load_stage(sb, 0);
    for (int it = 0; it < NC; it++) {
        if (it + 1 < NC) {
            load_stage(sb + ((it + 1) & 1) * T3_STAGE, (it + 1) << 5);
            CP_WAIT(1);
        } else CP_WAIT(0);
        __syncthreads();

        const uint32_t st = sb + (it & 1) * T3_STAGE;
        const uint32_t aB = st + wm * 32 * 80 + a_off;
        const uint32_t bB = st + T3_TILE_A + wn * 32 * 80 + b_off;

#pragma unroll
        for (int kk = 0; kk < 2; kk++) {
            const uint32_t ko = kk * 32;
            uint32_t ah[2][4], bb[2][4];
#pragma unroll
            for (int mt = 0; mt < 2; mt++) LDSM4(ah[mt], aB + mt * 16 * 80 + ko);
#pragma unroll
            for (int bt = 0; bt < 2; bt++) LDSM4(bb[bt], bB + bt * 16 * 80 + ko);
#pragma unroll
            for (int mt = 0; mt < 2; mt++)
#pragma unroll
                for (int nt = 0; nt < 4; nt++) {
                    const int bt = nt >> 1, hh = (nt & 1) << 1;
                    MMA_FP16(acc[mt][nt], ah[mt], bb[bt][hh], bb[bt][hh + 1]);
                }
        }
        __syncthreads();
    }

    const int r0 = bm + wm * 32 + (lane >> 2);
    const int c0 = bn + wn * 32 + (lane & 3) * 2;
#pragma unroll
    for (int mt = 0; mt < 2; mt++)
#pragma unroll
        for (int nt = 0; nt < 4; nt++) {
            float* p0 = C + (size_t)(r0 + mt * 16) * N + c0 + nt * 8;
            *(float2*)p0                   = make_float2(acc[mt][nt][0], acc[mt][nt][1]);
            *(float2*)(p0 + (size_t)8 * N) = make_float2(acc[mt][nt][2], acc[mt][nt][3]);
        }
}

// ---------------- fp32 -> fp16 hi/lo split ----------------
__device__ __forceinline__ void split_fp16(float v, __half& h, __half& l) {
    h = __float2half_rn(v);
    l = __float2half_rn(v - __half2float(h));
}

// ---------------- vectorized prep (x4) ----------------
#define V_JOB0 (M_ROWS * DM / 4)
#define V_JOB1 (N_XZ * DM / 4)
#define V_JOB2 (DM * DI / 4)
#define V_JOB3 (N_COMB * DI / 4)
#define V_PREP (V_JOB0 + V_JOB1 + V_JOB2 + V_JOB3)
__global__ void prep_k(const float* __restrict__ x, const float* __restrict__ Win,
                       const float* __restrict__ Wout,
                       const float* __restrict__ Wdt, const float* __restrict__ Wx) {
    int v = blockIdx.x * 256 + threadIdx.x;
    if (v < V_JOB0) {
        float4 f = *(const float4*)(x + v * 4);
        __half h0, l0, h1, l1, h2, l2, h3, l3;
        split_fp16(f.x, h0, l0); split_fp16(f.y, h1, l1);
        split_fp16(f.z, h2, l2); split_fp16(f.w, h3, l3);
        *(__half2*)(g_xh + v * 4)     = __halves2half2(h0, h1);
        *(__half2*)(g_xh + v * 4 + 2) = __halves2half2(h2, h3);
        *(__half2*)(g_xl + v * 4)     = __halves2half2(l0, l1);
        *(__half2*)(g_xl + v * 4 + 2) = __halves2half2(l2, l3);
        return;
    }
    v -= V_JOB0;
    if (v < V_JOB1) {
        float4 f = *(const float4*)(Win + v * 4);
        *(__half2*)(g_wi16 + v * 4)     = __halves2half2(__float2half_rn(f.x), __float2half_rn(f.y));
        *(__half2*)(g_wi16 + v * 4 + 2) = __halves2half2(__float2half_rn(f.z), __float2half_rn(f.w));
        return;
    }
    v -= V_JOB1;
    if (v < V_JOB2) {
        float4 f = *(const float4*)(Wout + v * 4);
        *(__half2*)(g_wo16 + v * 4)     = __halves2half2(__float2half_rn(f.x), __float2half_rn(f.y));
        *(__half2*)(g_wo16 + v * 4 + 2) = __halves2half2(__float2half_rn(f.z), __float2half_rn(f.w));
        return;
    }
    v -= V_JOB2;
    if (v < V_JOB3) {
        int idx = v * 4;
        int row = idx / DI, col = idx - row * DI;
        float4 f = make_float4(0.f, 0.f, 0.f, 0.f);
        if (row < DI)           f = *(const float4*)(Wdt + idx);
        else if (row < DI + 32) f = *(const float4*)(Wx + (row - DI) * DI + col);
        *(__half2*)(g_wc16 + idx)     = __halves2half2(__float2half_rn(f.x), __float2half_rn(f.y));
        *(__half2*)(g_wc16 + idx + 2) = __halves2half2(__float2half_rn(f.z), __float2half_rn(f.w));
    }
}

// ---------------- conv + SiLU, vectorized x4 ----------------
__global__ void conv_silu_k(const float* __restrict__ Wc) {
    int v = blockIdx.x * 256 + threadIdx.x;
    if (v >= M_ROWS * DI / 4) return;
    const int dpr = DI / 4;
    int m  = v / dpr;
    int d4 = (v - m * dpr) * 4;
    int l  = m & (L_SEQ - 1);

    float4 w[4];
#pragma unroll
    for (int q = 0; q < 4; q++) w[q] = *(const float4*)(Wc + (d4 + q) * 4);

    const float* xr = g_xz + (size_t)m * N_XZ + d4;
    float4 s0 = *(const float4*)xr;
    float r0 = s0.x * w[0].w, r1 = s0.y * w[1].w, r2 = s0.z * w[2].w, r3 = s0.w * w[3].w;
    if (l >= 1) {
        float4 s1 = *(const float4*)(xr - N_XZ);
        r0 = fmaf(s1.x, w[0].z, r0); r1 = fmaf(s1.y, w[1].z, r1);
        r2 = fmaf(s1.z, w[2].z, r2); r3 = fmaf(s1.w, w[3].z, r3);
    }
    if (l >= 2) {
        float4 s2 = *(const float4*)(xr - 2 * N_XZ);
        r0 = fmaf(s2.x, w[0].y, r0); r1 = fmaf(s2.y, w[1].y, r1);
        r2 = fmaf(s2.z, w[2].y, r2); r3 = fmaf(s2.w, w[3].y, r3);
    }
    if (l >= 3) {
        float4 s3 = *(const float4*)(xr - 3 * N_XZ);
        r0 = fmaf(s3.x, w[0].x, r0); r1 = fmaf(s3.y, w[1].x, r1);
        r2 = fmaf(s3.z, w[2].x, r2); r3 = fmaf(s3.w, w[3].x, r3);
    }
    float v0 = __fdividef(r0, 1.f + __expf(-r0));
    float v1 = __fdividef(r1, 1.f + __expf(-r1));
    float v2 = __fdividef(r2, 1.f + __expf(-r2));
    float v3 = __fdividef(r3, 1.f + __expf(-r3));

    __half h0,l0h,h1,l1h,h2,l2h,h3,l3h;
    split_fp16(v0, h0, l0h); split_fp16(v1, h1, l1h);
    split_fp16(v2, h2, l2h); split_fp16(v3, h3, l3h);
    const size_t o = (size_t)m * DI + d4;
    *(__half2*)(g_xch + o)     = __halves2half2(h0, h1);
    *(__half2*)(g_xch + o + 2) = __halves2half2(h2, h3);
    *(__half2*)(g_xcl + o)     = __halves2half2(l0h, l1h);
    *(__half2*)(g_xcl + o + 2) = __halves2half2(l2h, l3h);
}

// ---------------- scan helpers ----------------
__device__ __forceinline__ void pow16(float p, float* pw) {
    pw[0]=p;          pw[1]=p*p;        pw[2]=pw[1]*p;     pw[3]=pw[1]*pw[1];
    pw[4]=pw[3]*p;    pw[5]=pw[3]*pw[1];pw[6]=pw[3]*pw[2]; pw[7]=pw[3]*pw[3];
    pw[8]=pw[7]*p;    pw[9]=pw[7]*pw[1];pw[10]=pw[7]*pw[2];pw[11]=pw[7]*pw[3];
    pw[12]=pw[7]*pw[4];pw[13]=pw[7]*pw[5];pw[14]=pw[7]*pw[6];pw[15]=pw[7]*pw[7];
}
__device__ __forceinline__ bool geo_check(const float* Alog, float* A) {
#pragma unroll
    for (int s = 0; s < DS; s++) A[s] = -__expf(Alog[s]);
    bool geo = true;
#pragma unroll
    for (int s = 0; s < DS; s++)
        geo = geo && (fabsf(A[s] - (float)(s + 1) * A[0]) <= 1e-5f * fabsf(A[s]));
    return geo;
}
__device__ __forceinline__ float softplus_f(float x) {
    return (x > 20.f) ? x : log1pf(__expf(x));
}

#define PF 8   // prefetch batch

// ---------------- scan phase A: decay + h_end only ----------------
__global__ __launch_bounds__(128)
void scan_a(const float* __restrict__ Alog, const float* __restrict__ bdt) {
    __shared__ float sB[CL * 16];
    const int d = blockIdx.x * 128 + threadIdx.x;
    const int c = blockIdx.y, b = blockIdx.z;
    const int m0 = b * L_SEQ + c * CL;
    for (int e = threadIdx.x; e < CL * 16; e += 128) {
        int l = e >> 4, q = e & 15;
        sB[e] = g_dx[(size_t)(m0 + l) * N_COMB + DI + q];
    }
    __syncthreads();

    float A[DS];
    const bool geo = geo_check(Alog, A);
    const float bd = bdt[d];
    float h[DS];
#pragma unroll
    for (int s = 0; s < DS; s++) h[s] = 0.f;
    const size_t base = ((size_t)(b * CCH + c) * DS) * DI + d;

    float pf[PF];
#pragma unroll
    for (int i = 0; i < PF; i++)
        pf[i] = g_dx[(size_t)(m0 + i) * N_COMB + d];

    if (geo) {
        const float A0 = A[0];
        float pp = 1.f;
        for (int l0 = 0; l0 < CL; l0 += PF) {
            float cur[PF];
#pragma unroll
            for (int i = 0; i < PF; i++) cur[i] = pf[i];
            if (l0 + PF < CL) {
#pragma unroll
                for (int i = 0; i < PF; i++)
                    pf[i] = g_dx[(size_t)(m0 + l0 + PF + i) * N_COMB + d];
            }
#pragma unroll
            for (int u = 0; u < PF; u++) {
                const int l = l0 + u;
                float dt = softplus_f(cur[u] + bd);
                float p = __expf(A0 * dt);
                pp *= p;
                float pw[DS]; pow16(p, pw);
#pragma unroll
                for (int s = 0; s < DS; s++)
                    h[s] = fmaf(pw[s], h[s], dt * sB[l * 16 + s]);
            }
        }
        float dw[DS]; pow16(pp, dw);
#pragma unroll
        for (int s = 0; s < DS; s++) {
            g_cdec[base + (size_t)s * DI] = dw[s];
            g_hend[base + (size_t)s * DI] = h[s];
        }
    } else {
        float dec[DS];
#pragma unroll
        for (int s = 0; s < DS; s++) dec[s] = 1.f;
        for (int l0 = 0; l0 < CL; l0 += PF) {
            float cur[PF];
#pragma unroll
            for (int i = 0; i < PF; i++) cur[i] = pf[i];
            if (l0 + PF < CL) {
#pragma unroll
                for (int i = 0; i < PF; i++)
                    pf[i] = g_dx[(size_t)(m0 + l0 + PF + i) * N_COMB + d];
            }
#pragma unroll
            for (int u = 0; u < PF; u++) {
                const int l = l0 + u;
                float dt = softplus_f(cur[u] + bd);
#pragma unroll
                for (int s = 0; s < DS; s++) {
                    float dA = __expf(A[s] * dt);
                    dec[s] *= dA;
                    h[s] = fmaf(dA, h[s], dt * sB[l * 16 + s]);
                }
            }
        }
#pragma unroll
        for (int s = 0; s < DS; s++) {
            g_cdec[base + (size_t)s * DI] = dec[s];
            g_hend[base + (size_t)s * DI] = h[s];
        }
    }
}

// ---------------- scan phase B: chunk combine (prefetched) ----------------
__global__ __launch_bounds__(128)
void scan_b() {
    const int d = blockIdx.x * 128 + threadIdx.x;
    const int b = blockIdx.y;
    float H[DS];
#pragma unroll
    for (int s = 0; s < DS; s++) H[s] = 0.f;

    float pc[DS], ph[DS];
    {
        const size_t b0 = ((size_t)(b * CCH) * DS) * DI + d;
#pragma unroll
        for (int s = 0; s < DS; s++) {
            pc[s] = g_cdec[b0 + (size_t)s * DI];
            ph[s] = g_hend[b0 + (size_t)s * DI];
        }
    }
    for (int c = 0; c < CCH; c++) {
        float cc[DS], ch[DS];
#pragma unroll
        for (int s = 0; s < DS; s++) { cc[s] = pc[s]; ch[s] = ph[s]; }
        if (c + 1 < CCH) {
            const size_t bn = ((size_t)(b * CCH + c + 1) * DS) * DI + d;
#pragma unroll
            for (int s = 0; s < DS; s++) {
                pc[s] = g_cdec[bn + (size_t)s * DI];
                ph[s] = g_hend[bn + (size_t)s * DI];
            }
        }
        const size_t base = ((size_t)(b * CCH + c) * DS) * DI + d;
#pragma unroll
        for (int s = 0; s < DS; s++) {
            g_h0[base + (size_t)s * DI] = H[s];
            H[s] = fmaf(cc[s], H[s], ch[s]);
        }
    }
}

// ---------------- scan phase C: exact rescan from H0 + gate ----------------
__global__ __launch_bounds__(128)
void scan_c(const float* __restrict__ Alog, const float* __restrict__ Dp,
            const float* __restrict__ bdt) {
    __shared__ float sBC[CL * 32];
    const int d = blockIdx.x * 128 + threadIdx.x;
    const int c = blockIdx.y, b = blockIdx.z;
    const int m0 = b * L_SEQ + c * CL;
    for (int e = threadIdx.x; e < CL * 32; e += 128) {
        int l = e >> 5, q = e & 31;
        sBC[e] = g_dx[(size_t)(m0 + l) * N_COMB + DI + q];
    }
    __syncthreads();

    float A[DS];
    const bool geo = geo_check(Alog, A);
    const float Dd = Dp[d];
    const float bd = bdt[d];
    float h[DS];
    const size_t base = ((size_t)(b * CCH + c) * DS) * DI + d;
#pragma unroll
    for (int s = 0; s < DS; s++) h[s] = g_h0[base + (size_t)s * DI];

    float pf_d[PF], pf_z[PF], pf_x[PF];
#pragma unroll
    for (int i = 0; i < PF; i++) {
        const size_t m = m0 + i;
        pf_d[i] = g_dx[m * N_COMB + d];
        pf_z[i] = g_xz[m * N_XZ + DI + d];
        pf_x[i] = __half2float(g_xch[m * DI + d]) +
                  __half2float(g_xcl[m * DI + d]);
    }

    if (geo) {
        const float A0 = A[0];
        for (int l0 = 0; l0 < CL; l0 += PF) {
            float cd[PF], cz[PF], cx[PF];
#pragma unroll
            for (int i = 0; i < PF; i++) {
                cd[i] = pf_d[i]; cz[i] = pf_z[i]; cx[i] = pf_x[i];
            }
            if (l0 + PF < CL) {
#pragma unroll
                for (int i = 0; i < PF; i++) {
                    const size_t m = m0 + l0 + PF + i;
                    pf_d[i] = g_dx[m * N_COMB + d];
                    pf_z[i] = g_xz[m * N_XZ + DI + d];
                    pf_x[i] = __half2float(g_xch[m * DI + d]) +
                              __half2float(g_xcl[m * DI + d]);
                }
            }
#pragma unroll
            for (int u = 0; u < PF; u++) {
                const int l = l0 + u;
                const size_t m = m0 + l;
                float dt = softplus_f(cd[u] + bd);
                float p = __expf(A0 * dt);
                float pw[DS]; pow16(p, pw);
                float y0=0.f, y1=0.f, y2=0.f, y3=0.f;
#pragma unroll
                for (int s = 0; s < DS; s++) {
                    h[s] = fmaf(pw[s], h[s], dt * sBC[l * 32 + s]);
                    float t = h[s] * sBC[l * 32 + 16 + s];
                    if ((s&3)==0) y0+=t; else if ((s&3)==1) y1+=t;
                    else if ((s&3)==2) y2+=t; else y3+=t;
                }
                float y = (y0 + y1) + (y2 + y3);
                float z = cz[u];
                float o = (y + Dd * cx[u]) * __fdividef(z, 1.f + __expf(-z));
                g_y16[m * DI + d] = __float2half_rn(o);
            }
        }
    } else {
        for (int l0 = 0; l0 < CL; l0 += PF) {
            float cd[PF], cz[PF], cx[PF];
#pragma unroll
            for (int i = 0; i < PF; i++) {
                cd[i] = pf_d[i]; cz[i] = pf_z[i]; cx[i] = pf_x[i];
            }
            if (l0 + PF < CL) {
#pragma unroll
                for (int i = 0; i < PF; i++) {
                    const size_t m = m0 + l0 + PF + i;
                    pf_d[i] = g_dx[m * N_COMB + d];
                    pf_z[i] = g_xz[m * N_XZ + DI + d];
                    pf_x[i] = __half2float(g_xch[m * DI + d]) +
                              __half2float(g_xcl[m * DI + d]);
                }
            }
#pragma unroll
            for (int u = 0; u < PF; u++) {
                const int l = l0 + u;
                const size_t m = m0 + l;
                float dt = softplus_f(cd[u] + bd);
                float y0=0.f, y1=0.f, y2=0.f, y3=0.f;
#pragma unroll
                for (int s = 0; s < DS; s++) {
                    float dA = __expf(A[s] * dt);
                    h[s] = fmaf(dA, h[s], dt * sBC[l * 32 + s]);
                    float t = h[s] * sBC[l * 32 + 16 + s];
                    if ((s&3)==0) y0+=t; else if ((s&3)==1) y1+=t;
                    else if ((s&3)==2) y2+=t; else y3+=t;
                }
                float y = (y0 + y1) + (y2 + y3);
                float z = cz[u];
                float o = (y + Dd * cx[u]) * __fdividef(z, 1.f + __expf(-z));
                g_y16[m * DI + d] = __float2half_rn(o);
            }
        }
    }
}

// ---------------- launch ----------------
extern "C" void kernel_launch(void* const* d_in, const int* in_sizes, int n_in,
                              void* d_out, int out_size) {
    const float* x      = (const float*)d_in[0];
    const float* W_in   = (const float*)d_in[1];
    const float* W_conv = (const float*)d_in[2];
    const float* W_x    = (const float*)d_in[3];
    const float* W_dt   = (const float*)d_in[4];
    const float* b_dt   = (const float*)d_in[5];
    const float* A_log  = (const float*)d_in[6];
    const float* Dp     = (const float*)d_in[7];
    const float* W_out  = (const float*)d_in[8];
    float* out = (float*)d_out;

    cudaFuncSetAttribute(gemm_f16t<true>,
                         cudaFuncAttributeMaxDynamicSharedMemorySize, F2_SMEM);
    cudaFuncSetAttribute(gemm_f16t<false>,
                         cudaFuncAttributeMaxDynamicSharedMemorySize, F2_SMEM);
    cudaFuncSetAttribute(gemm_fp16,
                         cudaFuncAttributeMaxDynamicSharedMemorySize, T3_SMEM);

    float *xz, *dx;
    __half *xh, *xl, *wi16, *wc16, *xch, *xcl, *y16, *wo16;
    cudaGetSymbolAddress((void**)&xz,   g_xz);
    cudaGetSymbolAddress((void**)&dx,   g_dx);
    cudaGetSymbolAddress((void**)&xh,   g_xh);   cudaGetSymbolAddress((void**)&xl,   g_xl);
    cudaGetSymbolAddress((void**)&wi16, g_wi16); cudaGetSymbolAddress((void**)&wc16, g_wc16);
    cudaGetSymbolAddress((void**)&xch,  g_xch);  cudaGetSymbolAddress((void**)&xcl,  g_xcl);
    cudaGetSymbolAddress((void**)&y16,  g_y16);  cudaGetSymbolAddress((void**)&wo16, g_wo16);

    prep_k<<<(V_PREP + 255)/256, 256>>>(x, W_in, W_out, W_dt, W_x);

    // xz x-part: 2-term, cols [0, DI)
    gemm_f16t<true><<<dim3(DI/128, M_ROWS/128), 256, F2_SMEM>>>(
        xh, xl, wi16, xz, M_ROWS, N_XZ, DM, 0);
    // xz z-part: 1-term, cols [DI, N_XZ)
    gemm_f16t<false><<<dim3((N_XZ - DI)/128, M_ROWS/128), 256, F2_SMEM>>>(
        xh, xl, wi16, xz, M_ROWS, N_XZ, DM, DI);
    conv_silu_k<<<(M_ROWS*DI/4 + 255)/256, 256>>>(W_conv);
    // dx delta-part: 1-term, cols [0, DI)
    gemm_f16t<false><<<dim3(DI/128, M_ROWS/128), 256, F2_SMEM>>>(
        xch, xcl, wc16, dx, M_ROWS, N_COMB, DI, 0);
    // dx B/C-part: 2-term, cols [DI, N_COMB)
    gemm_f16t<true><<<dim3((N_COMB - DI)/128, M_ROWS/128), 256, F2_SMEM>>>(
        xch, xcl, wc16, dx, M_ROWS, N_COMB, DI, DI);
    scan_a<<<dim3(DI/128, CCH, BATCH), 128>>>(A_log, b_dt);
    scan_b<<<dim3(DI/128, BATCH), 128>>>();
    scan_c<<<dim3(DI/128, CCH, BATCH), 128>>>(A_log, Dp, b_dt);
    gemm_fp16<<<dim3(DM/128, M_ROWS/64), 256, T3_SMEM>>>(
        y16, wo16, out, M_ROWS, DM, DI);
}

// round 15
// speedup vs baseline: 1.1424x; 1.1424x over previous
#include <cuda_runtime.h>
#include <cuda_bf16.h>
#include <cuda_fp16.h>
#include <math.h>
#include <stdint.h>

// ---------------- problem sizes ----------------
#define L_SEQ  2048
#define BATCH  2
#define DM     768
#define DI     1536
#define DS     16
#define M_ROWS (BATCH * L_SEQ)   // 4096
#define N_XZ   (2 * DI)          // 3072
#define N_COMB 1664              // 1536 + 32, padded to 13*128
#define CCH    32                // scan chunks
#define CL     64                // chunk length

// ---------------- scratch globals ----------------
__device__ __align__(128) float g_xz[M_ROWS * N_XZ];
__device__ __align__(128) float g_dx[M_ROWS * N_COMB];

__device__ __align__(128) __half g_xh [M_ROWS * DM],  g_xl [M_ROWS * DM];
__device__ __align__(128) __half g_wi16[N_XZ * DM];
__device__ __align__(128) __half g_wc16[N_COMB * DI];
__device__ __align__(128) __half g_xch[M_ROWS * DI];
__device__ __align__(128) __half g_y16 [M_ROWS * DI];
__device__ __align__(128) __half g_wo16[DM * DI];

__device__ __align__(128) float g_cdec[BATCH * CCH * DS * DI];
__device__ __align__(128) float g_hend[BATCH * CCH * DS * DI];
__device__ __align__(128) float g_h0  [BATCH * CCH * DS * DI];

// ---------------- PTX helpers (plain sm_80+ PTX; NO tcgen05) --------
__device__ __forceinline__ uint32_t smem_u32(const void* p) {
    uint32_t a;
    asm("{ .reg .u64 t; cvta.to.shared.u64 t, %1; cvt.u32.u64 %0, t; }" : "=r"(a) : "l"(p));
    return a;
}
#define CP_ASYNC16(dst, src) \
    asm volatile("cp.async.cg.shared.global [%0], [%1], 16;" :: "r"(dst), "l"(src))
#define CP_COMMIT() asm volatile("cp.async.commit_group;")
#define CP_WAIT(n)  asm volatile("cp.async.wait_group %0;" :: "n"(n))
#define LDSM4(r, a) \
    asm volatile("ldmatrix.sync.aligned.m8n8.x4.shared.b16 {%0,%1,%2,%3}, [%4];" \
                 : "=r"((r)[0]), "=r"((r)[1]), "=r"((r)[2]), "=r"((r)[3]) : "r"(a))
#define MMA_FP16(c, a, b0, b1) \
    asm volatile("mma.sync.aligned.m16n8k16.row.col.f32.f16.f16.f32 " \
                 "{%0,%1,%2,%3}, {%4,%5,%6,%7}, {%8,%9}, {%0,%1,%2,%3};" \
                 : "+f"((c)[0]), "+f"((c)[1]), "+f"((c)[2]), "+f"((c)[3]) \
                 : "r"((a)[0]), "r"((a)[1]), "r"((a)[2]), "r"((a)[3]), \
                   "r"(b0), "r"(b1))

// ---------------- templated fp16 GEMM: C = (Ah[+Al]) B^T ------------------
// 128x128 tile, BK=32, 80B rows, 2-stage cp.async, 2 CTA/SM.
#define F2_TILE  10240            // 128 rows * 80 bytes
#define F2_STAGE 30720            // Ah, Al, B
#define F2_SMEM  (2 * F2_STAGE)   // 61440

template<bool TWO>
__global__ __launch_bounds__(256, 2)
void gemm_f16t(const __half* __restrict__ Ah, const __half* __restrict__ Al,
               const __half* __restrict__ B, float* __restrict__ C,
               int M, int N, int K, int col0) {
    extern __shared__ __align__(128) char smem[];
    const uint32_t sb = smem_u32(smem);
    const int tid  = threadIdx.x;
    const int lane = tid & 31;
    const int wid  = tid >> 5;
    const int wm   = wid & 3;
    const int wn   = wid >> 2;
    const int bm   = blockIdx.y * 128;
    const int bn   = col0 + blockIdx.x * 128;

    const __half* srcs[3] = { Ah + (size_t)bm * K, Al + (size_t)bm * K,
                              B + (size_t)bn * K };

    auto load_stage = [&](uint32_t stb, int k0) {
#pragma unroll
        for (int i = 0; i < 6; i++) {
            const int c = i * 256 + tid;
            const int t = c >> 9, w = c & 511, r = w >> 2, j = w & 3;
            if (!TWO && t == 1) continue;      // compile-time eliminated
            CP_ASYNC16(stb + t * F2_TILE + r * 80 + j * 16,
                       srcs[t] + (size_t)r * K + k0 + j * 8);
        }
        CP_COMMIT();
    };

    float acc[2][8][4];
#pragma unroll
    for (int mt = 0; mt < 2; mt++)
#pragma unroll
        for (int nt = 0; nt < 8; nt++)
#pragma unroll
            for (int q = 0; q < 4; q++) acc[mt][nt][q] = 0.f;

    const uint32_t a_off = (uint32_t)((lane & 15) * 80 + (lane >> 4) * 16);
    const uint32_t b_off = (uint32_t)((((lane >> 4) << 3) + (lane & 7)) * 80 +
                                      ((lane >> 3) & 1) * 16);

    const int NC = K >> 5;
    load_stage(sb, 0);

    for (int it = 0; it < NC; it++) {
        if (it + 1 < NC) {
            load_stage(sb + ((it + 1) & 1) * F2_STAGE, (it + 1) << 5);
            CP_WAIT(1);
        } else {
            CP_WAIT(0);
        }
        __syncthreads();

        const uint32_t st  = sb + (it & 1) * F2_STAGE;
        const uint32_t aHb = st + wm * 32 * 80 + a_off;
        const uint32_t aLb = st + F2_TILE + wm * 32 * 80 + a_off;
        const uint32_t bBb = st + 2 * F2_TILE + wn * 64 * 80 + b_off;

#pragma unroll
        for (int kk = 0; kk < 2; kk++) {
            const uint32_t ko = kk * 32;
            uint32_t ah[2][4], bb[4][4];
#pragma unroll
            for (int mt = 0; mt < 2; mt++)
                LDSM4(ah[mt], aHb + mt * 16 * 80 + ko);
#pragma unroll
            for (int bt = 0; bt < 4; bt++)
                LDSM4(bb[bt], bBb + bt * 16 * 80 + ko);
#pragma unroll
            for (int mt = 0; mt < 2; mt++)
#pragma unroll
                for (int nt = 0; nt < 8; nt++) {
                    const int bt = nt >> 1, hh = (nt & 1) << 1;
                    MMA_FP16(acc[mt][nt], ah[mt], bb[bt][hh], bb[bt][hh + 1]);
                }
            if (TWO) {
                uint32_t al[2][4];
#pragma unroll
                for (int mt = 0; mt < 2; mt++)
                    LDSM4(al[mt], aLb + mt * 16 * 80 + ko);
#pragma unroll
                for (int mt = 0; mt < 2; mt++)
#pragma unroll
                    for (int nt = 0; nt < 8; nt++) {
                        const int bt = nt >> 1, hh = (nt & 1) << 1;
                        MMA_FP16(acc[mt][nt], al[mt], bb[bt][hh], bb[bt][hh + 1]);
                    }
            }
        }
        __syncthreads();
    }

    const int r0 = bm + wm * 32 + (lane >> 2);
    const int c0 = bn + wn * 64 + (lane & 3) * 2;
#pragma unroll
    for (int mt = 0; mt < 2; mt++)
#pragma unroll
        for (int nt = 0; nt < 8; nt++) {
            float* p0 = C + (size_t)(r0 + mt * 16) * N + c0 + nt * 8;
            *(float2*)p0                   = make_float2(acc[mt][nt][0], acc[mt][nt][1]);
            *(float2*)(p0 + (size_t)8 * N) = make_float2(acc[mt][nt][2], acc[mt][nt][3]);
        }
}

// ---------------- fp16 single-term GEMM (final projection) ----------------
#define T3_TILE_A 5120
#define T3_STAGE  15360
#define T3_SMEM   (2 * T3_STAGE)

__global__ __launch_bounds__(256, 3)
void gemm_fp16(const __half* __restrict__ A, const __half* __restrict__ B,
               float* __restrict__ C, int M, int N, int K) {
    extern __shared__ __align__(128) char smem[];
    const uint32_t sb = smem_u32(smem);
    const int tid = threadIdx.x, lane = tid & 31, wid = tid >> 5;
    const int wm = wid & 1, wn = wid >> 1;
    const int bm = blockIdx.y * 64, bn = blockIdx.x * 128;

    const __half* srcA = A + (size_t)bm * K;
    const __half* srcB = B + (size_t)bn * K;

    float acc[2][4][4];
#pragma unroll
    for (int mt = 0; mt < 2; mt++)
#pragma unroll
        for (int nt = 0; nt < 4; nt++)
#pragma unroll
            for (int q = 0; q < 4; q++) acc[mt][nt][q] = 0.f;

    const uint32_t a_off = (uint32_t)((lane & 15) * 80 + (lane >> 4) * 16);
    const uint32_t b_off = (uint32_t)((((lane >> 4) << 3) + (lane & 7)) * 80 +
                                      ((lane >> 3) & 1) * 16);
    const int NC = K >> 5;

    auto load_stage = [&](uint32_t stb, int k0) {
#pragma unroll
        for (int i = 0; i < 3; i++) {
            int c = i * 256 + tid;
            if (c < 256) {
                int r = c >> 2, j = c & 3;
                CP_ASYNC16(stb + r * 80 + j * 16, srcA + (size_t)r * K + k0 + j * 8);
            } else {
                int c2 = c - 256, r = c2 >> 2, j = c2 & 3;
                CP_ASYNC16(stb + T3_TILE_A + r * 80 + j * 16,
                           srcB + (size_t)r * K + k0 + j * 8);
            }
        }
        CP_COMMIT();
    };

    load_stage(sb, 0);
    for (int it = 0; it < NC; it++) {
        if (it + 1 < NC) {
            load_stage(sb + ((it + 1) & 1) * T3_STAGE, (it + 1) << 5);
            CP_WAIT(1);
        } else CP_WAIT(0);
        __syncthreads();

        const uint32_t st = sb + (it & 1) * T3_STAGE;
        const uint32_t aB = st + wm * 32 * 80 + a_off;
        const uint32_t bB = st + T3_TILE_A + wn * 32 * 80 + b_off;

#pragma unroll
        for (int kk = 0; kk < 2; kk++) {
            const uint32_t ko = kk * 32;
            uint32_t ah[2][4], bb[2][4];
#pragma unroll
            for (int mt = 0; mt < 2; mt++) LDSM4(ah[mt], aB + mt * 16 * 80 + ko);
#pragma unroll
            for (int bt = 0; bt < 2; bt++) LDSM4(bb[bt], bB + bt * 16 * 80 + ko);
#pragma unroll
            for (int mt = 0; mt < 2; mt++)
#pragma unroll
                for (int nt = 0; nt < 4; nt++) {
                    const int bt = nt >> 1, hh = (nt & 1) << 1;
                    MMA_FP16(acc[mt][nt], ah[mt], bb[bt][hh], bb[bt][hh + 1]);
                }
        }
        __syncthreads();
    }

    const int r0 = bm + wm * 32 + (lane >> 2);
    const int c0 = bn + wn * 32 + (lane & 3) * 2;
#pragma unroll
    for (int mt = 0; mt < 2; mt++)
#pragma unroll
        for (int nt = 0; nt < 4; nt++) {
            float* p0 = C + (size_t)(r0 + mt * 16) * N + c0 + nt * 8;
            *(float2*)p0                   = make_float2(acc[mt][nt][0], acc[mt][nt][1]);
            *(float2*)(p0 + (size_t)8 * N) = make_float2(acc[mt][nt][2], acc[mt][nt][3]);
        }
}

// ---------------- fp32 -> fp16 hi/lo split ----------------
__device__ __forceinline__ void split_fp16(float v, __half& h, __half& l) {
    h = __float2half_rn(v);
    l = __float2half_rn(v - __half2float(h));
}

// ---------------- vectorized prep (x4) ----------------
#define V_JOB0 (M_ROWS * DM / 4)
#define V_JOB1 (N_XZ * DM / 4)
#define V_JOB2 (DM * DI / 4)
#define V_JOB3 (N_COMB * DI / 4)
#define V_PREP (V_JOB0 + V_JOB1 + V_JOB2 + V_JOB3)
__global__ void prep_k(const float* __restrict__ x, const float* __restrict__ Win,
                       const float* __restrict__ Wout,
                       const float* __restrict__ Wdt, const float* __restrict__ Wx) {
    int v = blockIdx.x * 256 + threadIdx.x;
    if (v < V_JOB0) {
        float4 f = *(const float4*)(x + v * 4);
        __half h0, l0, h1, l1, h2, l2, h3, l3;
        split_fp16(f.x, h0, l0); split_fp16(f.y, h1, l1);
        split_fp16(f.z, h2, l2); split_fp16(f.w, h3, l3);
        *(__half2*)(g_xh + v * 4)     = __halves2half2(h0, h1);
        *(__half2*)(g_xh + v * 4 + 2) = __halves2half2(h2, h3);
        *(__half2*)(g_xl + v * 4)     = __halves2half2(l0, l1);
        *(__half2*)(g_xl + v * 4 + 2) = __halves2half2(l2, l3);
        return;
    }
    v -= V_JOB0;
    if (v < V_JOB1) {
        float4 f = *(const float4*)(Win + v * 4);
        *(__half2*)(g_wi16 + v * 4)     = __halves2half2(__float2half_rn(f.x), __float2half_rn(f.y));
        *(__half2*)(g_wi16 + v * 4 + 2) = __halves2half2(__float2half_rn(f.z), __float2half_rn(f.w));
        return;
    }
    v -= V_JOB1;
    if (v < V_JOB2) {
        float4 f = *(const float4*)(Wout + v * 4);
        *(__half2*)(g_wo16 + v * 4)     = __halves2half2(__float2half_rn(f.x), __float2half_rn(f.y));
        *(__half2*)(g_wo16 + v * 4 + 2) = __halves2half2(__float2half_rn(f.z), __float2half_rn(f.w));
        return;
    }
    v -= V_JOB2;
    if (v < V_JOB3) {
        int idx = v * 4;
        int row = idx / DI, col = idx - row * DI;
        float4 f = make_float4(0.f, 0.f, 0.f, 0.f);
        if (row < DI)           f = *(const float4*)(Wdt + idx);
        else if (row < DI + 32) f = *(const float4*)(Wx + (row - DI) * DI + col);
        *(__half2*)(g_wc16 + idx)     = __halves2half2(__float2half_rn(f.x), __float2half_rn(f.y));
        *(__half2*)(g_wc16 + idx + 2) = __halves2half2(__float2half_rn(f.z), __float2half_rn(f.w));
    }
}

// ---------------- conv + SiLU, vectorized x4 (fp16 hi output only) --------
__global__ void conv_silu_k(const float* __restrict__ Wc) {
    int v = blockIdx.x * 256 + threadIdx.x;
    if (v >= M_ROWS * DI / 4) return;
    const int dpr = DI / 4;
    int m  = v / dpr;
    int d4 = (v - m * dpr) * 4;
    int l  = m & (L_SEQ - 1);

    float4 w[4];
#pragma unroll
    for (int q = 0; q < 4; q++) w[q] = *(const float4*)(Wc + (d4 + q) * 4);

    const float* xr = g_xz + (size_t)m * N_XZ + d4;
    float4 s0 = *(const float4*)xr;
    float r0 = s0.x * w[0].w, r1 = s0.y * w[1].w, r2 = s0.z * w[2].w, r3 = s0.w * w[3].w;
    if (l >= 1) {
        float4 s1 = *(const float4*)(xr - N_XZ);
        r0 = fmaf(s1.x, w[0].z, r0); r1 = fmaf(s1.y, w[1].z, r1);
        r2 = fmaf(s1.z, w[2].z, r2); r3 = fmaf(s1.w, w[3].z, r3);
    }
    if (l >= 2) {
        float4 s2 = *(const float4*)(xr - 2 * N_XZ);
        r0 = fmaf(s2.x, w[0].y, r0); r1 = fmaf(s2.y, w[1].y, r1);
        r2 = fmaf(s2.z, w[2].y, r2); r3 = fmaf(s2.w, w[3].y, r3);
    }
    if (l >= 3) {
        float4 s3 = *(const float4*)(xr - 3 * N_XZ);
        r0 = fmaf(s3.x, w[0].x, r0); r1 = fmaf(s3.y, w[1].x, r1);
        r2 = fmaf(s3.z, w[2].x, r2); r3 = fmaf(s3.w, w[3].x, r3);
    }
    float v0 = __fdividef(r0, 1.f + __expf(-r0));
    float v1 = __fdividef(r1, 1.f + __expf(-r1));
    float v2 = __fdividef(r2, 1.f + __expf(-r2));
    float v3 = __fdividef(r3, 1.f + __expf(-r3));

    const size_t o = (size_t)m * DI + d4;
    *(__half2*)(g_xch + o)     = __halves2half2(__float2half_rn(v0), __float2half_rn(v1));
    *(__half2*)(g_xch + o + 2) = __halves2half2(__float2half_rn(v2), __float2half_rn(v3));
}

// ---------------- scan helpers ----------------
__device__ __forceinline__ void pow16(float p, float* pw) {
    pw[0]=p;          pw[1]=p*p;        pw[2]=pw[1]*p;     pw[3]=pw[1]*pw[1];
    pw[4]=pw[3]*p;    pw[5]=pw[3]*pw[1];pw[6]=pw[3]*pw[2]; pw[7]=pw[3]*pw[3];
    pw[8]=pw[7]*p;    pw[9]=pw[7]*pw[1];pw[10]=pw[7]*pw[2];pw[11]=pw[7]*pw[3];
    pw[12]=pw[7]*pw[4];pw[13]=pw[7]*pw[5];pw[14]=pw[7]*pw[6];pw[15]=pw[7]*pw[7];
}
__device__ __forceinline__ bool geo_check(const float* Alog, float* A) {
#pragma unroll
    for (int s = 0; s < DS; s++) A[s] = -__expf(Alog[s]);
    bool geo = true;
#pragma unroll
    for (int s = 0; s < DS; s++)
        geo = geo && (fabsf(A[s] - (float)(s + 1) * A[0]) <= 1e-5f * fabsf(A[s]));
    return geo;
}
__device__ __forceinline__ float softplus_f(float x) {
    return (x > 20.f) ? x : log1pf(__expf(x));
}

#define PF 8   // prefetch batch

// ---------------- scan phase A: decay + h_end only ----------------
__global__ __launch_bounds__(128)
void scan_a(const float* __restrict__ Alog, const float* __restrict__ bdt) {
    __shared__ float sB[CL * 16];
    const int d = blockIdx.x * 128 + threadIdx.x;
    const int c = blockIdx.y, b = blockIdx.z;
    const int m0 = b * L_SEQ + c * CL;
    for (int e = threadIdx.x; e < CL * 16; e += 128) {
        int l = e >> 4, q = e & 15;
        sB[e] = g_dx[(size_t)(m0 + l) * N_COMB + DI + q];
    }
    __syncthreads();

    float A[DS];
    const bool geo = geo_check(Alog, A);
    const float bd = bdt[d];
    float h[DS];
#pragma unroll
    for (int s = 0; s < DS; s++) h[s] = 0.f;
    const size_t base = ((size_t)(b * CCH + c) * DS) * DI + d;

    float pf[PF];
#pragma unroll
    for (int i = 0; i < PF; i++)
        pf[i] = g_dx[(size_t)(m0 + i) * N_COMB + d];

    if (geo) {
        const float A0 = A[0];
        float pp = 1.f;
        for (int l0 = 0; l0 < CL; l0 += PF) {
            float cur[PF];
#pragma unroll
            for (int i = 0; i < PF; i++) cur[i] = pf[i];
            if (l0 + PF < CL) {
#pragma unroll
                for (int i = 0; i < PF; i++)
                    pf[i] = g_dx[(size_t)(m0 + l0 + PF + i) * N_COMB + d];
            }
#pragma unroll
            for (int u = 0; u < PF; u++) {
                const int l = l0 + u;
                float dt = softplus_f(cur[u] + bd);
                float p = __expf(A0 * dt);
                pp *= p;
                float pw[DS]; pow16(p, pw);
#pragma unroll
                for (int s = 0; s < DS; s++)
                    h[s] = fmaf(pw[s], h[s], dt * sB[l * 16 + s]);
            }
        }
        float dw[DS]; pow16(pp, dw);
#pragma unroll
        for (int s = 0; s < DS; s++) {
            g_cdec[base + (size_t)s * DI] = dw[s];
            g_hend[base + (size_t)s * DI] = h[s];
        }
    } else {
        float dec[DS];
#pragma unroll
        for (int s = 0; s < DS; s++) dec[s] = 1.f;
        for (int l0 = 0; l0 < CL; l0 += PF) {
            float cur[PF];
#pragma unroll
            for (int i = 0; i < PF; i++) cur[i] = pf[i];
            if (l0 + PF < CL) {
#pragma unroll
                for (int i = 0; i < PF; i++)
                    pf[i] = g_dx[(size_t)(m0 + l0 + PF + i) * N_COMB + d];
            }
#pragma unroll
            for (int u = 0; u < PF; u++) {
                const int l = l0 + u;
                float dt = softplus_f(cur[u] + bd);
#pragma unroll
                for (int s = 0; s < DS; s++) {
                    float dA = __expf(A[s] * dt);
                    dec[s] *= dA;
                    h[s] = fmaf(dA, h[s], dt * sB[l * 16 + s]);
                }
            }
        }
#pragma unroll
        for (int s = 0; s < DS; s++) {
            g_cdec[base + (size_t)s * DI] = dec[s];
            g_hend[base + (size_t)s * DI] = h[s];
        }
    }
}

// ---------------- scan phase B: chunk combine (prefetched) ----------------
__global__ __launch_bounds__(128)
void scan_b() {
    const int d = blockIdx.x * 128 + threadIdx.x;
    const int b = blockIdx.y;
    float H[DS];
#pragma unroll
    for (int s = 0; s < DS; s++) H[s] = 0.f;

    float pc[DS], ph[DS];
    {
        const size_t b0 = ((size_t)(b * CCH) * DS) * DI + d;
#pragma unroll
        for (int s = 0; s < DS; s++) {
            pc[s] = g_cdec[b0 + (size_t)s * DI];
            ph[s] = g_hend[b0 + (size_t)s * DI];
        }
    }
    for (int c = 0; c < CCH; c++) {
        float cc[DS], ch[DS];
#pragma unroll
        for (int s = 0; s < DS; s++) { cc[s] = pc[s]; ch[s] = ph[s]; }
        if (c + 1 < CCH) {
            const size_t bn = ((size_t)(b * CCH + c + 1) * DS) * DI + d;
#pragma unroll
            for (int s = 0; s < DS; s++) {
                pc[s] = g_cdec[bn + (size_t)s * DI];
                ph[s] = g_hend[bn + (size_t)s * DI];
            }
        }
        const size_t base = ((size_t)(b * CCH + c) * DS) * DI + d;
#pragma unroll
        for (int s = 0; s < DS; s++) {
            g_h0[base + (size_t)s * DI] = H[s];
            H[s] = fmaf(cc[s], H[s], ch[s]);
        }
    }
}

// ---------------- scan phase C: exact rescan from H0 + gate ----------------
__global__ __launch_bounds__(128)
void scan_c(const float* __restrict__ Alog, const float* __restrict__ Dp,
            const float* __restrict__ bdt) {
    __shared__ float sBC[CL * 32];
    const int d = blockIdx.x * 128 + threadIdx.x;
    const int c = blockIdx.y, b = blockIdx.z;
    const int m0 = b * L_SEQ + c * CL;
    for (int e = threadIdx.x; e < CL * 32; e += 128) {
        int l = e >> 5, q = e & 31;
        sBC[e] = g_dx[(size_t)(m0 + l) * N_COMB + DI + q];
    }
    __syncthreads();

    float A[DS];
    const bool geo = geo_check(Alog, A);
    const float Dd = Dp[d];
    const float bd = bdt[d];
    float h[DS];
    const size_t base = ((size_t)(b * CCH + c) * DS) * DI + d;
#pragma unroll
    for (int s = 0; s < DS; s++) h[s] = g_h0[base + (size_t)s * DI];

    float pf_d[PF], pf_z[PF], pf_x[PF];
#pragma unroll
    for (int i = 0; i < PF; i++) {
        const size_t m = m0 + i;
        pf_d[i] = g_dx[m * N_COMB + d];
        pf_z[i] = g_xz[m * N_XZ + DI + d];
        pf_x[i] = __half2float(g_xch[m * DI + d]);
    }

    if (geo) {
        const float A0 = A[0];
        for (int l0 = 0; l0 < CL; l0 += PF) {
            float cd[PF], cz[PF], cx[PF];
#pragma unroll
            for (int i = 0; i < PF; i++) {
                cd[i] = pf_d[i]; cz[i] = pf_z[i]; cx[i] = pf_x[i];
            }
            if (l0 + PF < CL) {
#pragma unroll
                for (int i = 0; i < PF; i++) {
                    const size_t m = m0 + l0 + PF + i;
                    pf_d[i] = g_dx[m * N_COMB + d];
                    pf_z[i] = g_xz[m * N_XZ + DI + d];
                    pf_x[i] = __half2float(g_xch[m * DI + d]);
                }
            }
#pragma unroll
            for (int u = 0; u < PF; u++) {
                const int l = l0 + u;
                const size_t m = m0 + l;
                float dt = softplus_f(cd[u] + bd);
                float p = __expf(A0 * dt);
                float pw[DS]; pow16(p, pw);
                float y0=0.f, y1=0.f, y2=0.f, y3=0.f;
#pragma unroll
                for (int s = 0; s < DS; s++) {
                    h[s] = fmaf(pw[s], h[s], dt * sBC[l * 32 + s]);
                    float t = h[s] * sBC[l * 32 + 16 + s];
                    if ((s&3)==0) y0+=t; else if ((s&3)==1) y1+=t;
                    else if ((s&3)==2) y2+=t; else y3+=t;
                }
                float y = (y0 + y1) + (y2 + y3);
                float z = cz[u];
                float o = (y + Dd * cx[u]) * __fdividef(z, 1.f + __expf(-z));
                g_y16[m * DI + d] = __float2half_rn(o);
            }
        }
    } else {
        for (int l0 = 0; l0 < CL; l0 += PF) {
            float cd[PF], cz[PF], cx[PF];
#pragma unroll
            for (int i = 0; i < PF; i++) {
                cd[i] = pf_d[i]; cz[i] = pf_z[i]; cx[i] = pf_x[i];
            }
            if (l0 + PF < CL) {
#pragma unroll
                for (int i = 0; i < PF; i++) {
                    const size_t m = m0 + l0 + PF + i;
                    pf_d[i] = g_dx[m * N_COMB + d];
                    pf_z[i] = g_xz[m * N_XZ + DI + d];
                    pf_x[i] = __half2float(g_xch[m * DI + d]);
                }
            }
#pragma unroll
            for (int u = 0; u < PF; u++) {
                const int l = l0 + u;
                const size_t m = m0 + l;
                float dt = softplus_f(cd[u] + bd);
                float y0=0.f, y1=0.f, y2=0.f, y3=0.f;
#pragma unroll
                for (int s = 0; s < DS; s++) {
                    float dA = __expf(A[s] * dt);
                    h[s] = fmaf(dA, h[s], dt * sBC[l * 32 + s]);
                    float t = h[s] * sBC[l * 32 + 16 + s];
                    if ((s&3)==0) y0+=t; else if ((s&3)==1) y1+=t;
                    else if ((s&3)==2) y2+=t; else y3+=t;
                }
                float y = (y0 + y1) + (y2 + y3);
                float z = cz[u];
                float o = (y + Dd * cx[u]) * __fdividef(z, 1.f + __expf(-z));
                g_y16[m * DI + d] = __float2half_rn(o);
            }
        }
    }
}

// ---------------- launch ----------------
extern "C" void kernel_launch(void* const* d_in, const int* in_sizes, int n_in,
                              void* d_out, int out_size) {
    const float* x      = (const float*)d_in[0];
    const float* W_in   = (const float*)d_in[1];
    const float* W_conv = (const float*)d_in[2];
    const float* W_x    = (const float*)d_in[3];
    const float* W_dt   = (const float*)d_in[4];
    const float* b_dt   = (const float*)d_in[5];
    const float* A_log  = (const float*)d_in[6];
    const float* Dp     = (const float*)d_in[7];
    const float* W_out  = (const float*)d_in[8];
    float* out = (float*)d_out;

    cudaFuncSetAttribute(gemm_f16t<true>,
                         cudaFuncAttributeMaxDynamicSharedMemorySize, F2_SMEM);
    cudaFuncSetAttribute(gemm_f16t<false>,
                         cudaFuncAttributeMaxDynamicSharedMemorySize, F2_SMEM);
    cudaFuncSetAttribute(gemm_fp16,
                         cudaFuncAttributeMaxDynamicSharedMemorySize, T3_SMEM);

    float *xz, *dx;
    __half *xh, *xl, *wi16, *wc16, *xch, *y16, *wo16;
    cudaGetSymbolAddress((void**)&xz,   g_xz);
    cudaGetSymbolAddress((void**)&dx,   g_dx);
    cudaGetSymbolAddress((void**)&xh,   g_xh);   cudaGetSymbolAddress((void**)&xl,   g_xl);
    cudaGetSymbolAddress((void**)&wi16, g_wi16); cudaGetSymbolAddress((void**)&wc16, g_wc16);
    cudaGetSymbolAddress((void**)&xch,  g_xch);
    cudaGetSymbolAddress((void**)&y16,  g_y16);  cudaGetSymbolAddress((void**)&wo16, g_wo16);

    prep_k<<<(V_PREP + 255)/256, 256>>>(x, W_in, W_out, W_dt, W_x);

    // xz x-part: 2-term, cols [0, DI)
    gemm_f16t<true><<<dim3(DI/128, M_ROWS/128), 256, F2_SMEM>>>(
        xh, xl, wi16, xz, M_ROWS, N_XZ, DM, 0);
    // xz z-part: 1-term, cols [DI, N_XZ)
    gemm_f16t<false><<<dim3((N_XZ - DI)/128, M_ROWS/128), 256, F2_SMEM>>>(
        xh, xl, wi16, xz, M_ROWS, N_XZ, DM, DI);
    conv_silu_k<<<(M_ROWS*DI/4 + 255)/256, 256>>>(W_conv);
    // dx: all columns 1-term (single launch)
    gemm_f16t<false><<<dim3(N_COMB/128, M_ROWS/128), 256, F2_SMEM>>>(
        xch, xch, wc16, dx, M_ROWS, N_COMB, DI, 0);
    scan_a<<<dim3(DI/128, CCH, BATCH), 128>>>(A_log, b_dt);
    scan_b<<<dim3(DI/128, BATCH), 128>>>();
    scan_c<<<dim3(DI/128, CCH, BATCH), 128>>>(A_log, Dp, b_dt);
    gemm_fp16<<<dim3(DM/128, M_ROWS/64), 256, T3_SMEM>>>(
        y16, wo16, out, M_ROWS, DM, DI);
}

// round 16
// speedup vs baseline: 1.2344x; 1.0806x over previous
#include <cuda_runtime.h>
#include <cuda_bf16.h>
#include <cuda_fp16.h>
#include <math.h>
#include <stdint.h>

// ---------------- problem sizes ----------------
#define L_SEQ  2048
#define BATCH  2
#define DM     768
#define DI     1536
#define DS     16
#define M_ROWS (BATCH * L_SEQ)   // 4096
#define N_XZ   (2 * DI)          // 3072
#define N_COMB 1664              // 1536 + 32, padded to 13*128
#define CCH    32                // scan chunks
#define CL     64                // chunk length

// ---------------- scratch globals ----------------
__device__ __align__(128) float g_xz[M_ROWS * N_XZ];
__device__ __align__(128) float g_dx[M_ROWS * N_COMB];

__device__ __align__(128) __half g_xh [M_ROWS * DM];
__device__ __align__(128) __half g_wi16[N_XZ * DM];
__device__ __align__(128) __half g_wc16[N_COMB * DI];
__device__ __align__(128) __half g_xch[M_ROWS * DI];
__device__ __align__(128) __half g_y16 [M_ROWS * DI];
__device__ __align__(128) __half g_wo16[DM * DI];

__device__ __align__(128) float g_cdec[BATCH * CCH * DS * DI];
__device__ __align__(128) float g_hend[BATCH * CCH * DS * DI];
__device__ __align__(128) float g_h0  [BATCH * CCH * DS * DI];

// ---------------- PTX helpers (plain sm_80+ PTX; NO tcgen05) --------
__device__ __forceinline__ uint32_t smem_u32(const void* p) {
    uint32_t a;
    asm("{ .reg .u64 t; cvta.to.shared.u64 t, %1; cvt.u32.u64 %0, t; }" : "=r"(a) : "l"(p));
    return a;
}
#define CP_ASYNC16(dst, src) \
    asm volatile("cp.async.cg.shared.global [%0], [%1], 16;" :: "r"(dst), "l"(src))
#define CP_COMMIT() asm volatile("cp.async.commit_group;")
#define CP_WAIT(n)  asm volatile("cp.async.wait_group %0;" :: "n"(n))
#define LDSM4(r, a) \
    asm volatile("ldmatrix.sync.aligned.m8n8.x4.shared.b16 {%0,%1,%2,%3}, [%4];" \
                 : "=r"((r)[0]), "=r"((r)[1]), "=r"((r)[2]), "=r"((r)[3]) : "r"(a))
#define MMA_FP16(c, a, b0, b1) \
    asm volatile("mma.sync.aligned.m16n8k16.row.col.f32.f16.f16.f32 " \
                 "{%0,%1,%2,%3}, {%4,%5,%6,%7}, {%8,%9}, {%0,%1,%2,%3};" \
                 : "+f"((c)[0]), "+f"((c)[1]), "+f"((c)[2]), "+f"((c)[3]) \
                 : "r"((a)[0]), "r"((a)[1]), "r"((a)[2]), "r"((a)[3]), \
                   "r"(b0), "r"(b1))

// ---------------- 1-term fp16 GEMM: C = A B^T --------------------
// 128x128 tile, BK=32, 80B rows, 2-stage cp.async, 2 CTA/SM.
#define F1_TILE  10240            // 128 rows * 80 bytes
#define F1_STAGE 20480            // A, B
#define F1_SMEM  (2 * F1_STAGE)   // 40960

__global__ __launch_bounds__(256, 2)
void gemm_f16(const __half* __restrict__ A, const __half* __restrict__ B,
              float* __restrict__ C, int M, int N, int K) {
    extern __shared__ __align__(128) char smem[];
    const uint32_t sb = smem_u32(smem);
    const int tid  = threadIdx.x;
    const int lane = tid & 31;
    const int wid  = tid >> 5;
    const int wm   = wid & 3;
    const int wn   = wid >> 2;
    const int bm   = blockIdx.y * 128;
    const int bn   = blockIdx.x * 128;

    const __half* srcs[2] = { A + (size_t)bm * K, B + (size_t)bn * K };

    auto load_stage = [&](uint32_t stb, int k0) {
#pragma unroll
        for (int i = 0; i < 4; i++) {
            const int c = i * 256 + tid;
            const int t = c >> 9, w = c & 511, r = w >> 2, j = w & 3;
            CP_ASYNC16(stb + t * F1_TILE + r * 80 + j * 16,
                       srcs[t] + (size_t)r * K + k0 + j * 8);
        }
        CP_COMMIT();
    };

    float acc[2][8][4];
#pragma unroll
    for (int mt = 0; mt < 2; mt++)
#pragma unroll
        for (int nt = 0; nt < 8; nt++)
#pragma unroll
            for (int q = 0; q < 4; q++) acc[mt][nt][q] = 0.f;

    const uint32_t a_off = (uint32_t)((lane & 15) * 80 + (lane >> 4) * 16);
    const uint32_t b_off = (uint32_t)((((lane >> 4) << 3) + (lane & 7)) * 80 +
                                      ((lane >> 3) & 1) * 16);

    const int NC = K >> 5;
    load_stage(sb, 0);

    for (int it = 0; it < NC; it++) {
        if (it + 1 < NC) {
            load_stage(sb + ((it + 1) & 1) * F1_STAGE, (it + 1) << 5);
            CP_WAIT(1);
        } else {
            CP_WAIT(0);
        }
        __syncthreads();

        const uint32_t st  = sb + (it & 1) * F1_STAGE;
        const uint32_t aBp = st + wm * 32 * 80 + a_off;
        const uint32_t bBp = st + F1_TILE + wn * 64 * 80 + b_off;

#pragma unroll
        for (int kk = 0; kk < 2; kk++) {
            const uint32_t ko = kk * 32;
            uint32_t ah[2][4], bb[4][4];
#pragma unroll
            for (int mt = 0; mt < 2; mt++)
                LDSM4(ah[mt], aBp + mt * 16 * 80 + ko);
#pragma unroll
            for (int bt = 0; bt < 4; bt++)
                LDSM4(bb[bt], bBp + bt * 16 * 80 + ko);
#pragma unroll
            for (int mt = 0; mt < 2; mt++)
#pragma unroll
                for (int nt = 0; nt < 8; nt++) {
                    const int bt = nt >> 1, hh = (nt & 1) << 1;
                    MMA_FP16(acc[mt][nt], ah[mt], bb[bt][hh], bb[bt][hh + 1]);
                }
        }
        __syncthreads();
    }

    const int r0 = bm + wm * 32 + (lane >> 2);
    const int c0 = bn + wn * 64 + (lane & 3) * 2;
#pragma unroll
    for (int mt = 0; mt < 2; mt++)
#pragma unroll
        for (int nt = 0; nt < 8; nt++) {
            float* p0 = C + (size_t)(r0 + mt * 16) * N + c0 + nt * 8;
            *(float2*)p0                   = make_float2(acc[mt][nt][0], acc[mt][nt][1]);
            *(float2*)(p0 + (size_t)8 * N) = make_float2(acc[mt][nt][2], acc[mt][nt][3]);
        }
}

// ---------------- fp16 GEMM for final projection (64x128 tile) ------------
#define T3_TILE_A 5120
#define T3_STAGE  15360
#define T3_SMEM   (2 * T3_STAGE)

__global__ __launch_bounds__(256, 3)
void gemm_fp16(const __half* __restrict__ A, const __half* __restrict__ B,
               float* __restrict__ C, int M, int N, int K) {
    extern __shared__ __align__(128) char smem[];
    const uint32_t sb = smem_u32(smem);
    const int tid = threadIdx.x, lane = tid & 31, wid = tid >> 5;
    const int wm = wid & 1, wn = wid >> 1;
    const int bm = blockIdx.y * 64, bn = blockIdx.x * 128;

    const __half* srcA = A + (size_t)bm * K;
    const __half* srcB = B + (size_t)bn * K;

    float acc[2][4][4];
#pragma unroll
    for (int mt = 0; mt < 2; mt++)
#pragma unroll
        for (int nt = 0; nt < 4; nt++)
#pragma unroll
            for (int q = 0; q < 4; q++) acc[mt][nt][q] = 0.f;

    const uint32_t a_off = (uint32_t)((lane & 15) * 80 + (lane >> 4) * 16);
    const uint32_t b_off = (uint32_t)((((lane >> 4) << 3) + (lane & 7)) * 80 +
                                      ((lane >> 3) & 1) * 16);
    const int NC = K >> 5;

    auto load_stage = [&](uint32_t stb, int k0) {
#pragma unroll
        for (int i = 0; i < 3; i++) {
            int c = i * 256 + tid;
            if (c < 256) {
                int r = c >> 2, j = c & 3;
                CP_ASYNC16(stb + r * 80 + j * 16, srcA + (size_t)r * K + k0 + j * 8);
            } else {
                int c2 = c - 256, r = c2 >> 2, j = c2 & 3;
                CP_ASYNC16(stb + T3_TILE_A + r * 80 + j * 16,
                           srcB + (size_t)r * K + k0 + j * 8);
            }
        }
        CP_COMMIT();
    };

    load_stage(sb, 0);
    for (int it = 0; it < NC; it++) {
        if (it + 1 < NC) {
            load_stage(sb + ((it + 1) & 1) * T3_STAGE, (it + 1) << 5);
            CP_WAIT(1);
        } else CP_WAIT(0);
        __syncthreads();

        const uint32_t st = sb + (it & 1) * T3_STAGE;
        const uint32_t aB = st + wm * 32 * 80 + a_off;
        const uint32_t bB = st + T3_TILE_A + wn * 32 * 80 + b_off;

#pragma unroll
        for (int kk = 0; kk < 2; kk++) {
            const uint32_t ko = kk * 32;
            uint32_t ah[2][4], bb[2][4];
#pragma unroll
            for (int mt = 0; mt < 2; mt++) LDSM4(ah[mt], aB + mt * 16 * 80 + ko);
#pragma unroll
            for (int bt = 0; bt < 2; bt++) LDSM4(bb[bt], bB + bt * 16 * 80 + ko);
#pragma unroll
            for (int mt = 0; mt < 2; mt++)
#pragma unroll
                for (int nt = 0; nt < 4; nt++) {
                    const int bt = nt >> 1, hh = (nt & 1) << 1;
                    MMA_FP16(acc[mt][nt], ah[mt], bb[bt][hh], bb[bt][hh + 1]);
                }
        }
        __syncthreads();
    }

    const int r0 = bm + wm * 32 + (lane >> 2);
    const int c0 = bn + wn * 32 + (lane & 3) * 2;
#pragma unroll
    for (int mt = 0; mt < 2; mt++)
#pragma unroll
        for (int nt = 0; nt < 4; nt++) {
            float* p0 = C + (size_t)(r0 + mt * 16) * N + c0 + nt * 8;
            *(float2*)p0                   = make_float2(acc[mt][nt][0], acc[mt][nt][1]);
            *(float2*)(p0 + (size_t)8 * N) = make_float2(acc[mt][nt][2], acc[mt][nt][3]);
        }
}

// ---------------- vectorized prep (x4) ----------------
#define V_JOB0 (M_ROWS * DM / 4)
#define V_JOB1 (N_XZ * DM / 4)
#define V_JOB2 (DM * DI / 4)
#define V_JOB3 (N_COMB * DI / 4)
#define V_PREP (V_JOB0 + V_JOB1 + V_JOB2 + V_JOB3)
__global__ void prep_k(const float* __restrict__ x, const float* __restrict__ Win,
                       const float* __restrict__ Wout,
                       const float* __restrict__ Wdt, const float* __restrict__ Wx) {
    int v = blockIdx.x * 256 + threadIdx.x;
    if (v < V_JOB0) {
        float4 f = *(const float4*)(x + v * 4);
        *(__half2*)(g_xh + v * 4)     = __halves2half2(__float2half_rn(f.x), __float2half_rn(f.y));
        *(__half2*)(g_xh + v * 4 + 2) = __halves2half2(__float2half_rn(f.z), __float2half_rn(f.w));
        return;
    }
    v -= V_JOB0;
    if (v < V_JOB1) {
        float4 f = *(const float4*)(Win + v * 4);
        *(__half2*)(g_wi16 + v * 4)     = __halves2half2(__float2half_rn(f.x), __float2half_rn(f.y));
        *(__half2*)(g_wi16 + v * 4 + 2) = __halves2half2(__float2half_rn(f.z), __float2half_rn(f.w));
        return;
    }
    v -= V_JOB1;
    if (v < V_JOB2) {
        float4 f = *(const float4*)(Wout + v * 4);
        *(__half2*)(g_wo16 + v * 4)     = __halves2half2(__float2half_rn(f.x), __float2half_rn(f.y));
        *(__half2*)(g_wo16 + v * 4 + 2) = __halves2half2(__float2half_rn(f.z), __float2half_rn(f.w));
        return;
    }
    v -= V_JOB2;
    if (v < V_JOB3) {
        int idx = v * 4;
        int row = idx / DI, col = idx - row * DI;
        float4 f = make_float4(0.f, 0.f, 0.f, 0.f);
        if (row < DI)           f = *(const float4*)(Wdt + idx);
        else if (row < DI + 32) f = *(const float4*)(Wx + (row - DI) * DI + col);
        *(__half2*)(g_wc16 + idx)     = __halves2half2(__float2half_rn(f.x), __float2half_rn(f.y));
        *(__half2*)(g_wc16 + idx + 2) = __halves2half2(__float2half_rn(f.z), __float2half_rn(f.w));
    }
}

// ---------------- conv + SiLU, vectorized x4 (fp16 output) --------
__global__ void conv_silu_k(const float* __restrict__ Wc) {
    int v = blockIdx.x * 256 + threadIdx.x;
    if (v >= M_ROWS * DI / 4) return;
    const int dpr = DI / 4;
    int m  = v / dpr;
    int d4 = (v - m * dpr) * 4;
    int l  = m & (L_SEQ - 1);

    float4 w[4];
#pragma unroll
    for (int q = 0; q < 4; q++) w[q] = *(const float4*)(Wc + (d4 + q) * 4);

    const float* xr = g_xz + (size_t)m * N_XZ + d4;
    float4 s0 = *(const float4*)xr;
    float r0 = s0.x * w[0].w, r1 = s0.y * w[1].w, r2 = s0.z * w[2].w, r3 = s0.w * w[3].w;
    if (l >= 1) {
        float4 s1 = *(const float4*)(xr - N_XZ);
        r0 = fmaf(s1.x, w[0].z, r0); r1 = fmaf(s1.y, w[1].z, r1);
        r2 = fmaf(s1.z, w[2].z, r2); r3 = fmaf(s1.w, w[3].z, r3);
    }
    if (l >= 2) {
        float4 s2 = *(const float4*)(xr - 2 * N_XZ);
        r0 = fmaf(s2.x, w[0].y, r0); r1 = fmaf(s2.y, w[1].y, r1);
        r2 = fmaf(s2.z, w[2].y, r2); r3 = fmaf(s2.w, w[3].y, r3);
    }
    if (l >= 3) {
        float4 s3 = *(const float4*)(xr - 3 * N_XZ);
        r0 = fmaf(s3.x, w[0].x, r0); r1 = fmaf(s3.y, w[1].x, r1);
        r2 = fmaf(s3.z, w[2].x, r2); r3 = fmaf(s3.w, w[3].x, r3);
    }
    float v0 = __fdividef(r0, 1.f + __expf(-r0));
    float v1 = __fdividef(r1, 1.f + __expf(-r1));
    float v2 = __fdividef(r2, 1.f + __expf(-r2));
    float v3 = __fdividef(r3, 1.f + __expf(-r3));

    const size_t o = (size_t)m * DI + d4;
    *(__half2*)(g_xch + o)     = __halves2half2(__float2half_rn(v0), __float2half_rn(v1));
    *(__half2*)(g_xch + o + 2) = __halves2half2(__float2half_rn(v2), __float2half_rn(v3));
}

// ---------------- scan helpers ----------------
__device__ __forceinline__ void pow16(float p, float* pw) {
    pw[0]=p;          pw[1]=p*p;        pw[2]=pw[1]*p;     pw[3]=pw[1]*pw[1];
    pw[4]=pw[3]*p;    pw[5]=pw[3]*pw[1];pw[6]=pw[3]*pw[2]; pw[7]=pw[3]*pw[3];
    pw[8]=pw[7]*p;    pw[9]=pw[7]*pw[1];pw[10]=pw[7]*pw[2];pw[11]=pw[7]*pw[3];
    pw[12]=pw[7]*pw[4];pw[13]=pw[7]*pw[5];pw[14]=pw[7]*pw[6];pw[15]=pw[7]*pw[7];
}
__device__ __forceinline__ bool geo_check(const float* Alog, float* A) {
#pragma unroll
    for (int s = 0; s < DS; s++) A[s] = -__expf(Alog[s]);
    bool geo = true;
#pragma unroll
    for (int s = 0; s < DS; s++)
        geo = geo && (fabsf(A[s] - (float)(s + 1) * A[0]) <= 1e-5f * fabsf(A[s]));
    return geo;
}
__device__ __forceinline__ float softplus_f(float x) {
    return (x > 20.f) ? x : log1pf(__expf(x));
}

#define PF 8   // prefetch batch

// ---------------- scan phase A: decay + h_end only ----------------
__global__ __launch_bounds__(128)
void scan_a(const float* __restrict__ Alog, const float* __restrict__ bdt) {
    __shared__ float sB[CL * 16];
    const int d = blockIdx.x * 128 + threadIdx.x;
    const int c = blockIdx.y, b = blockIdx.z;
    const int m0 = b * L_SEQ + c * CL;
    for (int e = threadIdx.x; e < CL * 16; e += 128) {
        int l = e >> 4, q = e & 15;
        sB[e] = g_dx[(size_t)(m0 + l) * N_COMB + DI + q];
    }
    __syncthreads();

    float A[DS];
    const bool geo = geo_check(Alog, A);
    const float bd = bdt[d];
    float h[DS];
#pragma unroll
    for (int s = 0; s < DS; s++) h[s] = 0.f;
    const size_t base = ((size_t)(b * CCH + c) * DS) * DI + d;

    float pf[PF];
#pragma unroll
    for (int i = 0; i < PF; i++)
        pf[i] = g_dx[(size_t)(m0 + i) * N_COMB + d];

    if (geo) {
        const float A0 = A[0];
        float pp = 1.f;
        for (int l0 = 0; l0 < CL; l0 += PF) {
            float cur[PF];
#pragma unroll
            for (int i = 0; i < PF; i++) cur[i] = pf[i];
            if (l0 + PF < CL) {
#pragma unroll
                for (int i = 0; i < PF; i++)
                    pf[i] = g_dx[(size_t)(m0 + l0 + PF + i) * N_COMB + d];
            }
#pragma unroll
            for (int u = 0; u < PF; u++) {
                const int l = l0 + u;
                float dt = softplus_f(cur[u] + bd);
                float p = __expf(A0 * dt);
                pp *= p;
                float pw[DS]; pow16(p, pw);
#pragma unroll
                for (int s = 0; s < DS; s++)
                    h[s] = fmaf(pw[s], h[s], dt * sB[l * 16 + s]);
            }
        }
        float dw[DS]; pow16(pp, dw);
#pragma unroll
        for (int s = 0; s < DS; s++) {
            g_cdec[base + (size_t)s * DI] = dw[s];
            g_hend[base + (size_t)s * DI] = h[s];
        }
    } else {
        float dec[DS];
#pragma unroll
        for (int s = 0; s < DS; s++) dec[s] = 1.f;
        for (int l0 = 0; l0 < CL; l0 += PF) {
            float cur[PF];
#pragma unroll
            for (int i = 0; i < PF; i++) cur[i] = pf[i];
            if (l0 + PF < CL) {
#pragma unroll
                for (int i = 0; i < PF; i++)
                    pf[i] = g_dx[(size_t)(m0 + l0 + PF + i) * N_COMB + d];
            }
#pragma unroll
            for (int u = 0; u < PF; u++) {
                const int l = l0 + u;
                float dt = softplus_f(cur[u] + bd);
#pragma unroll
                for (int s = 0; s < DS; s++) {
                    float dA = __expf(A[s] * dt);
                    dec[s] *= dA;
                    h[s] = fmaf(dA, h[s], dt * sB[l * 16 + s]);
                }
            }
        }
#pragma unroll
        for (int s = 0; s < DS; s++) {
            g_cdec[base + (size_t)s * DI] = dec[s];
            g_hend[base + (size_t)s * DI] = h[s];
        }
    }
}

// ---------------- scan phase B: chunk combine (prefetched) ----------------
__global__ __launch_bounds__(128)
void scan_b() {
    const int d = blockIdx.x * 128 + threadIdx.x;
    const int b = blockIdx.y;
    float H[DS];
#pragma unroll
    for (int s = 0; s < DS; s++) H[s] = 0.f;

    float pc[DS], ph[DS];
    {
        const size_t b0 = ((size_t)(b * CCH) * DS) * DI + d;
#pragma unroll
        for (int s = 0; s < DS; s++) {
            pc[s] = g_cdec[b0 + (size_t)s * DI];
            ph[s] = g_hend[b0 + (size_t)s * DI];
        }
    }
    for (int c = 0; c < CCH; c++) {
        float cc[DS], ch[DS];
#pragma unroll
        for (int s = 0; s < DS; s++) { cc[s] = pc[s]; ch[s] = ph[s]; }
        if (c + 1 < CCH) {
            const size_t bn = ((size_t)(b * CCH + c + 1) * DS) * DI + d;
#pragma unroll
            for (int s = 0; s < DS; s++) {
                pc[s] = g_cdec[bn + (size_t)s * DI];
                ph[s] = g_hend[bn + (size_t)s * DI];
            }
        }
        const size_t base = ((size_t)(b * CCH + c) * DS) * DI + d;
#pragma unroll
        for (int s = 0; s < DS; s++) {
            g_h0[base + (size_t)s * DI] = H[s];
            H[s] = fmaf(cc[s], H[s], ch[s]);
        }
    }
}

// ---------------- scan phase C: exact rescan from H0 + gate ----------------
__global__ __launch_bounds__(128)
void scan_c(const float* __restrict__ Alog, const float* __restrict__ Dp,
            const float* __restrict__ bdt) {
    __shared__ float sBC[CL * 32];
    const int d = blockIdx.x * 128 + threadIdx.x;
    const int c = blockIdx.y, b = blockIdx.z;
    const int m0 = b * L_SEQ + c * CL;
    for (int e = threadIdx.x; e < CL * 32; e += 128) {
        int l = e >> 5, q = e & 31;
        sBC[e] = g_dx[(size_t)(m0 + l) * N_COMB + DI + q];
    }
    __syncthreads();

    float A[DS];
    const bool geo = geo_check(Alog, A);
    const float Dd = Dp[d];
    const float bd = bdt[d];
    float h[DS];
    const size_t base = ((size_t)(b * CCH + c) * DS) * DI + d;
#pragma unroll
    for (int s = 0; s < DS; s++) h[s] = g_h0[base + (size_t)s * DI];

    float pf_d[PF], pf_z[PF], pf_x[PF];
#pragma unroll
    for (int i = 0; i < PF; i++) {
        const size_t m = m0 + i;
        pf_d[i] = g_dx[m * N_COMB + d];
        pf_z[i] = g_xz[m * N_XZ + DI + d];
        pf_x[i] = __half2float(g_xch[m * DI + d]);
    }

    if (geo) {
        const float A0 = A[0];
        for (int l0 = 0; l0 < CL; l0 += PF) {
            float cd[PF], cz[PF], cx[PF];
#pragma unroll
            for (int i = 0; i < PF; i++) {
                cd[i] = pf_d[i]; cz[i] = pf_z[i]; cx[i] = pf_x[i];
            }
            if (l0 + PF < CL) {
#pragma unroll
                for (int i = 0; i < PF; i++) {
                    const size_t m = m0 + l0 + PF + i;
                    pf_d[i] = g_dx[m * N_COMB + d];
                    pf_z[i] = g_xz[m * N_XZ + DI + d];
                    pf_x[i] = __half2float(g_xch[m * DI + d]);
                }
            }
#pragma unroll
            for (int u = 0; u < PF; u++) {
                const int l = l0 + u;
                const size_t m = m0 + l;
                float dt = softplus_f(cd[u] + bd);
                float p = __expf(A0 * dt);
                float pw[DS]; pow16(p, pw);
                float y0=0.f, y1=0.f, y2=0.f, y3=0.f;
#pragma unroll
                for (int s = 0; s < DS; s++) {
                    h[s] = fmaf(pw[s], h[s], dt * sBC[l * 32 + s]);
                    float t = h[s] * sBC[l * 32 + 16 + s];
                    if ((s&3)==0) y0+=t; else if ((s&3)==1) y1+=t;
                    else if ((s&3)==2) y2+=t; else y3+=t;
                }
                float y = (y0 + y1) + (y2 + y3);
                float z = cz[u];
                float o = (y + Dd * cx[u]) * __fdividef(z, 1.f + __expf(-z));
                g_y16[m * DI + d] = __float2half_rn(o);
            }
        }
    } else {
        for (int l0 = 0; l0 < CL; l0 += PF) {
            float cd[PF], cz[PF], cx[PF];
#pragma unroll
            for (int i = 0; i < PF; i++) {
                cd[i] = pf_d[i]; cz[i] = pf_z[i]; cx[i] = pf_x[i];
            }
            if (l0 + PF < CL) {
#pragma unroll
                for (int i = 0; i < PF; i++) {
                    const size_t m = m0 + l0 + PF + i;
                    pf_d[i] = g_dx[m * N_COMB + d];
                    pf_z[i] = g_xz[m * N_XZ + DI + d];
                    pf_x[i] = __half2float(g_xch[m * DI + d]);
                }
            }
#pragma unroll
            for (int u = 0; u < PF; u++) {
                const int l = l0 + u;
                const size_t m = m0 + l;
                float dt = softplus_f(cd[u] + bd);
                float y0=0.f, y1=0.f, y2=0.f, y3=0.f;
#pragma unroll
                for (int s = 0; s < DS; s++) {
                    float dA = __expf(A[s] * dt);
                    h[s] = fmaf(dA, h[s], dt * sBC[l * 32 + s]);
                    float t = h[s] * sBC[l * 32 + 16 + s];
                    if ((s&3)==0) y0+=t; else if ((s&3)==1) y1+=t;
                    else if ((s&3)==2) y2+=t; else y3+=t;
                }
                float y = (y0 + y1) + (y2 + y3);
                float z = cz[u];
                float o = (y + Dd * cx[u]) * __fdividef(z, 1.f + __expf(-z));
                g_y16[m * DI + d] = __float2half_rn(o);
            }
        }
    }
}

// ---------------- launch ----------------
extern "C" void kernel_launch(void* const* d_in, const int* in_sizes, int n_in,
                              void* d_out, int out_size) {
    const float* x      = (const float*)d_in[0];
    const float* W_in   = (const float*)d_in[1];
    const float* W_conv = (const float*)d_in[2];
    const float* W_x    = (const float*)d_in[3];
    const float* W_dt   = (const float*)d_in[4];
    const float* b_dt   = (const float*)d_in[5];
    const float* A_log  = (const float*)d_in[6];
    const float* Dp     = (const float*)d_in[7];
    const float* W_out  = (const float*)d_in[8];
    float* out = (float*)d_out;

    cudaFuncSetAttribute(gemm_f16,
                         cudaFuncAttributeMaxDynamicSharedMemorySize, F1_SMEM);
    cudaFuncSetAttribute(gemm_fp16,
                         cudaFuncAttributeMaxDynamicSharedMemorySize, T3_SMEM);

    float *xz, *dx;
    __half *xh, *wi16, *wc16, *xch, *y16, *wo16;
    cudaGetSymbolAddress((void**)&xz,   g_xz);
    cudaGetSymbolAddress((void**)&dx,   g_dx);
    cudaGetSymbolAddress((void**)&xh,   g_xh);
    cudaGetSymbolAddress((void**)&wi16, g_wi16); cudaGetSymbolAddress((void**)&wc16, g_wc16);
    cudaGetSymbolAddress((void**)&xch,  g_xch);
    cudaGetSymbolAddress((void**)&y16,  g_y16);  cudaGetSymbolAddress((void**)&wo16, g_wo16);

    prep_k<<<(V_PREP + 255)/256, 256>>>(x, W_in, W_out, W_dt, W_x);

    // xz = x @ W_in^T   (single 1-term launch, full N_XZ)
    gemm_f16<<<dim3(N_XZ/128, M_ROWS/128), 256, F1_SMEM>>>(
        xh, wi16, xz, M_ROWS, N_XZ, DM);
    conv_silu_k<<<(M_ROWS*DI/4 + 255)/256, 256>>>(W_conv);
    // dx = xc @ [W_dt;W_x;0]^T  (1-term)
    gemm_f16<<<dim3(N_COMB/128, M_ROWS/128), 256, F1_SMEM>>>(
        xch, wc16, dx, M_ROWS, N_COMB, DI);
    scan_a<<<dim3(DI/128, CCH, BATCH), 128>>>(A_log, b_dt);
    scan_b<<<dim3(DI/128, BATCH), 128>>>();
    scan_c<<<dim3(DI/128, CCH, BATCH), 128>>>(A_log, Dp, b_dt);
    gemm_fp16<<<dim3(DM/128, M_ROWS/64), 256, T3_SMEM>>>(
        y16, wo16, out, M_ROWS, DM, DI);
}

// round 17
// speedup vs baseline: 1.3617x; 1.1031x over previous
#include <cuda_runtime.h>
#include <cuda_bf16.h>
#include <cuda_fp16.h>
#include <math.h>
#include <stdint.h>

// ---------------- problem sizes ----------------
#define L_SEQ  2048
#define BATCH  2
#define DM     768
#define DI     1536
#define DS     16
#define M_ROWS (BATCH * L_SEQ)   // 4096
#define N_XZ   (2 * DI)          // 3072
#define N_COMB 1664              // 1536 + 32, padded to 13*128
#define CCH    32                // scan chunks
#define CL     64                // chunk length

// ---------------- scratch globals ----------------
__device__ __align__(128) float g_xz[M_ROWS * N_XZ];
__device__ __align__(128) float g_dx[M_ROWS * N_COMB];

__device__ __align__(128) __half g_xh [M_ROWS * DM];
__device__ __align__(128) __half g_wi16[N_XZ * DM];
__device__ __align__(128) __half g_wc16[N_COMB * DI];
__device__ __align__(128) __half g_xch[M_ROWS * DI];
__device__ __align__(128) __half g_y16 [M_ROWS * DI];
__device__ __align__(128) __half g_wo16[DM * DI];

__device__ __align__(128) float g_cdec[BATCH * CCH * DS * DI];
__device__ __align__(128) float g_hend[BATCH * CCH * DS * DI];
__device__ __align__(128) float g_h0  [BATCH * CCH * DS * DI];

// ---------------- PTX helpers (plain sm_80+ PTX; NO tcgen05) --------
__device__ __forceinline__ uint32_t smem_u32(const void* p) {
    uint32_t a;
    asm("{ .reg .u64 t; cvta.to.shared.u64 t, %1; cvt.u32.u64 %0, t; }" : "=r"(a) : "l"(p));
    return a;
}
#define CP_ASYNC16(dst, src) \
    asm volatile("cp.async.cg.shared.global [%0], [%1], 16;" :: "r"(dst), "l"(src))
#define CP_COMMIT() asm volatile("cp.async.commit_group;")
#define CP_WAIT(n)  asm volatile("cp.async.wait_group %0;" :: "n"(n))
#define LDSM4(r, a) \
    asm volatile("ldmatrix.sync.aligned.m8n8.x4.shared.b16 {%0,%1,%2,%3}, [%4];" \
                 : "=r"((r)[0]), "=r"((r)[1]), "=r"((r)[2]), "=r"((r)[3]) : "r"(a))
#define MMA_FP16(c, a, b0, b1) \
    asm volatile("mma.sync.aligned.m16n8k16.row.col.f32.f16.f16.f32 " \
                 "{%0,%1,%2,%3}, {%4,%5,%6,%7}, {%8,%9}, {%0,%1,%2,%3};" \
                 : "+f"((c)[0]), "+f"((c)[1]), "+f"((c)[2]), "+f"((c)[3]) \
                 : "r"((a)[0]), "r"((a)[1]), "r"((a)[2]), "r"((a)[3]), \
                   "r"(b0), "r"(b1))

// ---------------- 1-term fp16 GEMM: C = A B^T, BK=64 --------------------
// 128x128 tile, BK=64; rows 144B (128B data + 16B pad, conflict-free
// ldmatrix: r*144 mod 128 = r*16); 2-stage cp.async; 2 CTA/SM.
#define F1_TILE  18432            // 128 rows * 144 bytes
#define F1_STAGE 36864            // A, B
#define F1_SMEM  (2 * F1_STAGE)   // 73728

__global__ __launch_bounds__(256, 2)
void gemm_f16(const __half* __restrict__ A, const __half* __restrict__ B,
              float* __restrict__ C, int M, int N, int K) {
    extern __shared__ __align__(128) char smem[];
    const uint32_t sb = smem_u32(smem);
    const int tid  = threadIdx.x;
    const int lane = tid & 31;
    const int wid  = tid >> 5;
    const int wm   = wid & 3;
    const int wn   = wid >> 2;
    const int bm   = blockIdx.y * 128;
    const int bn   = blockIdx.x * 128;

    const __half* srcs[2] = { A + (size_t)bm * K, B + (size_t)bn * K };

    // 2048 chunks of 16B per stage -> 8 per thread
    auto load_stage = [&](uint32_t stb, int k0) {
#pragma unroll
        for (int i = 0; i < 8; i++) {
            const int c = i * 256 + tid;
            const int t = c >> 10, w = c & 1023, r = w >> 3, j = w & 7;
            CP_ASYNC16(stb + t * F1_TILE + r * 144 + j * 16,
                       srcs[t] + (size_t)r * K + k0 + j * 8);
        }
        CP_COMMIT();
    };

    float acc[2][8][4];
#pragma unroll
    for (int mt = 0; mt < 2; mt++)
#pragma unroll
        for (int nt = 0; nt < 8; nt++)
#pragma unroll
            for (int q = 0; q < 4; q++) acc[mt][nt][q] = 0.f;

    const uint32_t a_off = (uint32_t)((lane & 15) * 144 + (lane >> 4) * 16);
    const uint32_t b_off = (uint32_t)((((lane >> 4) << 3) + (lane & 7)) * 144 +
                                      ((lane >> 3) & 1) * 16);

    const int NC = K >> 6;
    load_stage(sb, 0);

    for (int it = 0; it < NC; it++) {
        if (it + 1 < NC) {
            load_stage(sb + ((it + 1) & 1) * F1_STAGE, (it + 1) << 6);
            CP_WAIT(1);
        } else {
            CP_WAIT(0);
        }
        __syncthreads();

        const uint32_t st  = sb + (it & 1) * F1_STAGE;
        const uint32_t aBp = st + wm * 32 * 144 + a_off;
        const uint32_t bBp = st + F1_TILE + wn * 64 * 144 + b_off;

#pragma unroll
        for (int kk = 0; kk < 4; kk++) {
            const uint32_t ko = kk * 32;
            uint32_t ah[2][4], bb[4][4];
#pragma unroll
            for (int mt = 0; mt < 2; mt++)
                LDSM4(ah[mt], aBp + mt * 16 * 144 + ko);
#pragma unroll
            for (int bt = 0; bt < 4; bt++)
                LDSM4(bb[bt], bBp + bt * 16 * 144 + ko);
#pragma unroll
            for (int mt = 0; mt < 2; mt++)
#pragma unroll
                for (int nt = 0; nt < 8; nt++) {
                    const int bt = nt >> 1, hh = (nt & 1) << 1;
                    MMA_FP16(acc[mt][nt], ah[mt], bb[bt][hh], bb[bt][hh + 1]);
                }
        }
        __syncthreads();
    }

    const int r0 = bm + wm * 32 + (lane >> 2);
    const int c0 = bn + wn * 64 + (lane & 3) * 2;
#pragma unroll
    for (int mt = 0; mt < 2; mt++)
#pragma unroll
        for (int nt = 0; nt < 8; nt++) {
            float* p0 = C + (size_t)(r0 + mt * 16) * N + c0 + nt * 8;
            *(float2*)p0                   = make_float2(acc[mt][nt][0], acc[mt][nt][1]);
            *(float2*)(p0 + (size_t)8 * N) = make_float2(acc[mt][nt][2], acc[mt][nt][3]);
        }
}

// ---------------- fp16 GEMM for final projection (64x128 tile) ------------
#define T3_TILE_A 5120
#define T3_STAGE  15360
#define T3_SMEM   (2 * T3_STAGE)

__global__ __launch_bounds__(256, 3)
void gemm_fp16(const __half* __restrict__ A, const __half* __restrict__ B,
               float* __restrict__ C, int M, int N, int K) {
    extern __shared__ __align__(128) char smem[];
    const uint32_t sb = smem_u32(smem);
    const int tid = threadIdx.x, lane = tid & 31, wid = tid >> 5;
    const int wm = wid & 1, wn = wid >> 1;
    const int bm = blockIdx.y * 64, bn = blockIdx.x * 128;

    const __half* srcA = A + (size_t)bm * K;
    const __half* srcB = B + (size_t)bn * K;

    float acc[2][4][4];
#pragma unroll
    for (int mt = 0; mt < 2; mt++)
#pragma unroll
        for (int nt = 0; nt < 4; nt++)
#pragma unroll
            for (int q = 0; q < 4; q++) acc[mt][nt][q] = 0.f;

    const uint32_t a_off = (uint32_t)((lane & 15) * 80 + (lane >> 4) * 16);
    const uint32_t b_off = (uint32_t)((((lane >> 4) << 3) + (lane & 7)) * 80 +
                                      ((lane >> 3) & 1) * 16);
    const int NC = K >> 5;

    auto load_stage = [&](uint32_t stb, int k0) {
#pragma unroll
        for (int i = 0; i < 3; i++) {
            int c = i * 256 + tid;
            if (c < 256) {
                int r = c >> 2, j = c & 3;
                CP_ASYNC16(stb + r * 80 + j * 16, srcA + (size_t)r * K + k0 + j * 8);
            } else {
                int c2 = c - 256, r = c2 >> 2, j = c2 & 3;
                CP_ASYNC16(stb + T3_TILE_A + r * 80 + j * 16,
                           srcB + (size_t)r * K + k0 + j * 8);
            }
        }
        CP_COMMIT();
    };

    load_stage(sb, 0);
    for (int it = 0; it < NC; it++) {
        if (it + 1 < NC) {
            load_stage(sb + ((it + 1) & 1) * T3_STAGE, (it + 1) << 5);
            CP_WAIT(1);
        } else CP_WAIT(0);
        __syncthreads();

        const uint32_t st = sb + (it & 1) * T3_STAGE;
        const uint32_t aB = st + wm * 32 * 80 + a_off;
        const uint32_t bB = st + T3_TILE_A + wn * 32 * 80 + b_off;

#pragma unroll
        for (int kk = 0; kk < 2; kk++) {
            const uint32_t ko = kk * 32;
            uint32_t ah[2][4], bb[2][4];
#pragma unroll
            for (int mt = 0; mt < 2; mt++) LDSM4(ah[mt], aB + mt * 16 * 80 + ko);
#pragma unroll
            for (int bt = 0; bt < 2; bt++) LDSM4(bb[bt], bB + bt * 16 * 80 + ko);
#pragma unroll
            for (int mt = 0; mt < 2; mt++)
#pragma unroll
                for (int nt = 0; nt < 4; nt++) {
                    const int bt = nt >> 1, hh = (nt & 1) << 1;
                    MMA_FP16(acc[mt][nt], ah[mt], bb[bt][hh], bb[bt][hh + 1]);
                }
        }
        __syncthreads();
    }

    const int r0 = bm + wm * 32 + (lane >> 2);
    const int c0 = bn + wn * 32 + (lane & 3) * 2;
#pragma unroll
    for (int mt = 0; mt < 2; mt++)
#pragma unroll
        for (int nt = 0; nt < 4; nt++) {
            float* p0 = C + (size_t)(r0 + mt * 16) * N + c0 + nt * 8;
            *(float2*)p0                   = make_float2(acc[mt][nt][0], acc[mt][nt][1]);
            *(float2*)(p0 + (size_t)8 * N) = make_float2(acc[mt][nt][2], acc[mt][nt][3]);
        }
}

// ---------------- vectorized prep (x4) ----------------
#define V_JOB0 (M_ROWS * DM / 4)
#define V_JOB1 (N_XZ * DM / 4)
#define V_JOB2 (DM * DI / 4)
#define V_JOB3 (N_COMB * DI / 4)
#define V_PREP (V_JOB0 + V_JOB1 + V_JOB2 + V_JOB3)
__global__ void prep_k(const float* __restrict__ x, const float* __restrict__ Win,
                       const float* __restrict__ Wout,
                       const float* __restrict__ Wdt, const float* __restrict__ Wx) {
    int v = blockIdx.x * 256 + threadIdx.x;
    if (v < V_JOB0) {
        float4 f = *(const float4*)(x + v * 4);
        *(__half2*)(g_xh + v * 4)     = __halves2half2(__float2half_rn(f.x), __float2half_rn(f.y));
        *(__half2*)(g_xh + v * 4 + 2) = __halves2half2(__float2half_rn(f.z), __float2half_rn(f.w));
        return;
    }
    v -= V_JOB0;
    if (v < V_JOB1) {
        float4 f = *(const float4*)(Win + v * 4);
        *(__half2*)(g_wi16 + v * 4)     = __halves2half2(__float2half_rn(f.x), __float2half_rn(f.y));
        *(__half2*)(g_wi16 + v * 4 + 2) = __halves2half2(__float2half_rn(f.z), __float2half_rn(f.w));
        return;
    }
    v -= V_JOB1;
    if (v < V_JOB2) {
        float4 f = *(const float4*)(Wout + v * 4);
        *(__half2*)(g_wo16 + v * 4)     = __halves2half2(__float2half_rn(f.x), __float2half_rn(f.y));
        *(__half2*)(g_wo16 + v * 4 + 2) = __halves2half2(__float2half_rn(f.z), __float2half_rn(f.w));
        return;
    }
    v -= V_JOB2;
    if (v < V_JOB3) {
        int idx = v * 4;
        int row = idx / DI, col = idx - row * DI;
        float4 f = make_float4(0.f, 0.f, 0.f, 0.f);
        if (row < DI)           f = *(const float4*)(Wdt + idx);
        else if (row < DI + 32) f = *(const float4*)(Wx + (row - DI) * DI + col);
        *(__half2*)(g_wc16 + idx)     = __halves2half2(__float2half_rn(f.x), __float2half_rn(f.y));
        *(__half2*)(g_wc16 + idx + 2) = __halves2half2(__float2half_rn(f.z), __float2half_rn(f.w));
    }
}

// ---------------- conv + SiLU, vectorized x4 (fp16 output) --------
__global__ void conv_silu_k(const float* __restrict__ Wc) {
    int v = blockIdx.x * 256 + threadIdx.x;
    if (v >= M_ROWS * DI / 4) return;
    const int dpr = DI / 4;
    int m  = v / dpr;
    int d4 = (v - m * dpr) * 4;
    int l  = m & (L_SEQ - 1);

    float4 w[4];
#pragma unroll
    for (int q = 0; q < 4; q++) w[q] = *(const float4*)(Wc + (d4 + q) * 4);

    const float* xr = g_xz + (size_t)m * N_XZ + d4;
    float4 s0 = *(const float4*)xr;
    float r0 = s0.x * w[0].w, r1 = s0.y * w[1].w, r2 = s0.z * w[2].w, r3 = s0.w * w[3].w;
    if (l >= 1) {
        float4 s1 = *(const float4*)(xr - N_XZ);
        r0 = fmaf(s1.x, w[0].z, r0); r1 = fmaf(s1.y, w[1].z, r1);
        r2 = fmaf(s1.z, w[2].z, r2); r3 = fmaf(s1.w, w[3].z, r3);
    }
    if (l >= 2) {
        float4 s2 = *(const float4*)(xr - 2 * N_XZ);
        r0 = fmaf(s2.x, w[0].y, r0); r1 = fmaf(s2.y, w[1].y, r1);
        r2 = fmaf(s2.z, w[2].y, r2); r3 = fmaf(s2.w, w[3].y, r3);
    }
    if (l >= 3) {
        float4 s3 = *(const float4*)(xr - 3 * N_XZ);
        r0 = fmaf(s3.x, w[0].x, r0); r1 = fmaf(s3.y, w[1].x, r1);
        r2 = fmaf(s3.z, w[2].x, r2); r3 = fmaf(s3.w, w[3].x, r3);
    }
    float v0 = __fdividef(r0, 1.f + __expf(-r0));
    float v1 = __fdividef(r1, 1.f + __expf(-r1));
    float v2 = __fdividef(r2, 1.f + __expf(-r2));
    float v3 = __fdividef(r3, 1.f + __expf(-r3));

    const size_t o = (size_t)m * DI + d4;
    *(__half2*)(g_xch + o)     = __halves2half2(__float2half_rn(v0), __float2half_rn(v1));
    *(__half2*)(g_xch + o + 2) = __halves2half2(__float2half_rn(v2), __float2half_rn(v3));
}

// ---------------- scan helpers ----------------
__device__ __forceinline__ void pow16(float p, float* pw) {
    pw[0]=p;          pw[1]=p*p;        pw[2]=pw[1]*p;     pw[3]=pw[1]*pw[1];
    pw[4]=pw[3]*p;    pw[5]=pw[3]*pw[1];pw[6]=pw[3]*pw[2]; pw[7]=pw[3]*pw[3];
    pw[8]=pw[7]*p;    pw[9]=pw[7]*pw[1];pw[10]=pw[7]*pw[2];pw[11]=pw[7]*pw[3];
    pw[12]=pw[7]*pw[4];pw[13]=pw[7]*pw[5];pw[14]=pw[7]*pw[6];pw[15]=pw[7]*pw[7];
}
__device__ __forceinline__ bool geo_check(const float* Alog, float* A) {
#pragma unroll
    for (int s = 0; s < DS; s++) A[s] = -__expf(Alog[s]);
    bool geo = true;
#pragma unroll
    for (int s = 0; s < DS; s++)
        geo = geo && (fabsf(A[s] - (float)(s + 1) * A[0]) <= 1e-5f * fabsf(A[s]));
    return geo;
}
__device__ __forceinline__ float softplus_f(float x) {
    return (x > 20.f) ? x : log1pf(__expf(x));
}

#define PF 8   // prefetch batch

// ---------------- scan phase A: decay + h_end only ----------------
__global__ __launch_bounds__(128)
void scan_a(const float* __restrict__ Alog, const float* __restrict__ bdt) {
    __shared__ float sB[CL * 16];
    const int d = blockIdx.x * 128 + threadIdx.x;
    const int c = blockIdx.y, b = blockIdx.z;
    const int m0 = b * L_SEQ + c * CL;
    for (int e = threadIdx.x; e < CL * 16; e += 128) {
        int l = e >> 4, q = e & 15;
        sB[e] = g_dx[(size_t)(m0 + l) * N_COMB + DI + q];
    }
    __syncthreads();

    float A[DS];
    const bool geo = geo_check(Alog, A);
    const float bd = bdt[d];
    float h[DS];
#pragma unroll
    for (int s = 0; s < DS; s++) h[s] = 0.f;
    const size_t base = ((size_t)(b * CCH + c) * DS) * DI + d;

    float pf[PF];
#pragma unroll
    for (int i = 0; i < PF; i++)
        pf[i] = g_dx[(size_t)(m0 + i) * N_COMB + d];

    if (geo) {
        const float A0 = A[0];
        float pp = 1.f;
        for (int l0 = 0; l0 < CL; l0 += PF) {
            float cur[PF];
#pragma unroll
            for (int i = 0; i < PF; i++) cur[i] = pf[i];
            if (l0 + PF < CL) {
#pragma unroll
                for (int i = 0; i < PF; i++)
                    pf[i] = g_dx[(size_t)(m0 + l0 + PF + i) * N_COMB + d];
            }
#pragma unroll
            for (int u = 0; u < PF; u++) {
                const int l = l0 + u;
                float dt = softplus_f(cur[u] + bd);
                float p = __expf(A0 * dt);
                pp *= p;
                float pw[DS]; pow16(p, pw);
#pragma unroll
                for (int s = 0; s < DS; s++)
                    h[s] = fmaf(pw[s], h[s], dt * sB[l * 16 + s]);
            }
        }
        float dw[DS]; pow16(pp, dw);
#pragma unroll
        for (int s = 0; s < DS; s++) {
            g_cdec[base + (size_t)s * DI] = dw[s];
            g_hend[base + (size_t)s * DI] = h[s];
        }
    } else {
        float dec[DS];
#pragma unroll
        for (int s = 0; s < DS; s++) dec[s] = 1.f;
        for (int l0 = 0; l0 < CL; l0 += PF) {
            float cur[PF];
#pragma unroll
            for (int i = 0; i < PF; i++) cur[i] = pf[i];
            if (l0 + PF < CL) {
#pragma unroll
                for (int i = 0; i < PF; i++)
                    pf[i] = g_dx[(size_t)(m0 + l0 + PF + i) * N_COMB + d];
            }
#pragma unroll
            for (int u = 0; u < PF; u++) {
                const int l = l0 + u;
                float dt = softplus_f(cur[u] + bd);
#pragma unroll
                for (int s = 0; s < DS; s++) {
                    float dA = __expf(A[s] * dt);
                    dec[s] *= dA;
                    h[s] = fmaf(dA, h[s], dt * sB[l * 16 + s]);
                }
            }
        }
#pragma unroll
        for (int s = 0; s < DS; s++) {
            g_cdec[base + (size_t)s * DI] = dec[s];
            g_hend[base + (size_t)s * DI] = h[s];
        }
    }
}

// ---------------- scan phase B: chunk combine (prefetched) ----------------
__global__ __launch_bounds__(128)
void scan_b() {
    const int d = blockIdx.x * 128 + threadIdx.x;
    const int b = blockIdx.y;
    float H[DS];
#pragma unroll
    for (int s = 0; s < DS; s++) H[s] = 0.f;

    float pc[DS], ph[DS];
    {
        const size_t b0 = ((size_t)(b * CCH) * DS) * DI + d;
#pragma unroll
        for (int s = 0; s < DS; s++) {
            pc[s] = g_cdec[b0 + (size_t)s * DI];
            ph[s] = g_hend[b0 + (size_t)s * DI];
        }
    }
    for (int c = 0; c < CCH; c++) {
        float cc[DS], ch[DS];
#pragma unroll
        for (int s = 0; s < DS; s++) { cc[s] = pc[s]; ch[s] = ph[s]; }
        if (c + 1 < CCH) {
            const size_t bn = ((size_t)(b * CCH + c + 1) * DS) * DI + d;
#pragma unroll
            for (int s = 0; s < DS; s++) {
                pc[s] = g_cdec[bn + (size_t)s * DI];
                ph[s] = g_hend[bn + (size_t)s * DI];
            }
        }
        const size_t base = ((size_t)(b * CCH + c) * DS) * DI + d;
#pragma unroll
        for (int s = 0; s < DS; s++) {
            g_h0[base + (size_t)s * DI] = H[s];
            H[s] = fmaf(cc[s], H[s], ch[s]);
        }
    }
}

// ---------------- scan phase C: exact rescan from H0 + gate ----------------
__global__ __launch_bounds__(128)
void scan_c(const float* __restrict__ Alog, const float* __restrict__ Dp,
            const float* __restrict__ bdt) {
    __shared__ float sBC[CL * 32];
    const int d = blockIdx.x * 128 + threadIdx.x;
    const int c = blockIdx.y, b = blockIdx.z;
    const int m0 = b * L_SEQ + c * CL;
    for (int e = threadIdx.x; e < CL * 32; e += 128) {
        int l = e >> 5, q = e & 31;
        sBC[e] = g_dx[(size_t)(m0 + l) * N_COMB + DI + q];
    }
    __syncthreads();

    float A[DS];
    const bool geo = geo_check(Alog, A);
    const float Dd = Dp[d];
    const float bd = bdt[d];
    float h[DS];
    const size_t base = ((size_t)(b * CCH + c) * DS) * DI + d;
#pragma unroll
    for (int s = 0; s < DS; s++) h[s] = g_h0[base + (size_t)s * DI];

    float pf_d[PF], pf_z[PF], pf_x[PF];
#pragma unroll
    for (int i = 0; i < PF; i++) {
        const size_t m = m0 + i;
        pf_d[i] = g_dx[m * N_COMB + d];
        pf_z[i] = g_xz[m * N_XZ + DI + d];
        pf_x[i] = __half2float(g_xch[m * DI + d]);
    }

    if (geo) {
        const float A0 = A[0];
        for (int l0 = 0; l0 < CL; l0 += PF) {
            float cd[PF], cz[PF], cx[PF];
#pragma unroll
            for (int i = 0; i < PF; i++) {
                cd[i] = pf_d[i]; cz[i] = pf_z[i]; cx[i] = pf_x[i];
            }
            if (l0 + PF < CL) {
#pragma unroll
                for (int i = 0; i < PF; i++) {
                    const size_t m = m0 + l0 + PF + i;
                    pf_d[i] = g_dx[m * N_COMB + d];
                    pf_z[i] = g_xz[m * N_XZ + DI + d];
                    pf_x[i] = __half2float(g_xch[m * DI + d]);
                }
            }
#pragma unroll
            for (int u = 0; u < PF; u++) {
                const int l = l0 + u;
                const size_t m = m0 + l;
                float dt = softplus_f(cd[u] + bd);
                float p = __expf(A0 * dt);
                float pw[DS]; pow16(p, pw);
                float y0=0.f, y1=0.f, y2=0.f, y3=0.f;
#pragma unroll
                for (int s = 0; s < DS; s++) {
                    h[s] = fmaf(pw[s], h[s], dt * sBC[l * 32 + s]);
                    float t = h[s] * sBC[l * 32 + 16 + s];
                    if ((s&3)==0) y0+=t; else if ((s&3)==1) y1+=t;
                    else if ((s&3)==2) y2+=t; else y3+=t;
                }
                float y = (y0 + y1) + (y2 + y3);
                float z = cz[u];
                float o = (y + Dd * cx[u]) * __fdividef(z, 1.f + __expf(-z));
                g_y16[m * DI + d] = __float2half_rn(o);
            }
        }
    } else {
        for (int l0 = 0; l0 < CL; l0 += PF) {
            float cd[PF], cz[PF], cx[PF];
#pragma unroll
            for (int i = 0; i < PF; i++) {
                cd[i] = pf_d[i]; cz[i] = pf_z[i]; cx[i] = pf_x[i];
            }
            if (l0 + PF < CL) {
#pragma unroll
                for (int i = 0; i < PF; i++) {
                    const size_t m = m0 + l0 + PF + i;
                    pf_d[i] = g_dx[m * N_COMB + d];
                    pf_z[i] = g_xz[m * N_XZ + DI + d];
                    pf_x[i] = __half2float(g_xch[m * DI + d]);
                }
            }
#pragma unroll
            for (int u = 0; u < PF; u++) {
                const int l = l0 + u;
                const size_t m = m0 + l;
                float dt = softplus_f(cd[u] + bd);
                float y0=0.f, y1=0.f, y2=0.f, y3=0.f;
#pragma unroll
                for (int s = 0; s < DS; s++) {
                    float dA = __expf(A[s] * dt);
                    h[s] = fmaf(dA, h[s], dt * sBC[l * 32 + s]);
                    float t = h[s] * sBC[l * 32 + 16 + s];
                    if ((s&3)==0) y0+=t; else if ((s&3)==1) y1+=t;
                    else if ((s&3)==2) y2+=t; else y3+=t;
                }
                float y = (y0 + y1) + (y2 + y3);
                float z = cz[u];
                float o = (y + Dd * cx[u]) * __fdividef(z, 1.f + __expf(-z));
                g_y16[m * DI + d] = __float2half_rn(o);
            }
        }
    }
}

// ---------------- launch ----------------
extern "C" void kernel_launch(void* const* d_in, const int* in_sizes, int n_in,
                              void* d_out, int out_size) {
    const float* x      = (const float*)d_in[0];
    const float* W_in   = (const float*)d_in[1];
    const float* W_conv = (const float*)d_in[2];
    const float* W_x    = (const float*)d_in[3];
    const float* W_dt   = (const float*)d_in[4];
    const float* b_dt   = (const float*)d_in[5];
    const float* A_log  = (const float*)d_in[6];
    const float* Dp     = (const float*)d_in[7];
    const float* W_out  = (const float*)d_in[8];
    float* out = (float*)d_out;

    cudaFuncSetAttribute(gemm_f16,
                         cudaFuncAttributeMaxDynamicSharedMemorySize, F1_SMEM);
    cudaFuncSetAttribute(gemm_fp16,
                         cudaFuncAttributeMaxDynamicSharedMemorySize, T3_SMEM);

    float *xz, *dx;
    __half *xh, *wi16, *wc16, *xch, *y16, *wo16;
    cudaGetSymbolAddress((void**)&xz,   g_xz);
    cudaGetSymbolAddress((void**)&dx,   g_dx);
    cudaGetSymbolAddress((void**)&xh,   g_xh);
    cudaGetSymbolAddress((void**)&wi16, g_wi16); cudaGetSymbolAddress((void**)&wc16, g_wc16);
    cudaGetSymbolAddress((void**)&xch,  g_xch);
    cudaGetSymbolAddress((void**)&y16,  g_y16);  cudaGetSymbolAddress((void**)&wo16, g_wo16);

    prep_k<<<(V_PREP + 255)/256, 256>>>(x, W_in, W_out, W_dt, W_x);

    // xz = x @ W_in^T
    gemm_f16<<<dim3(N_XZ/128, M_ROWS/128), 256, F1_SMEM>>>(
        xh, wi16, xz, M_ROWS, N_XZ, DM);
    conv_silu_k<<<(M_ROWS*DI/4 + 255)/256, 256>>>(W_conv);
    // dx = xc @ [W_dt;W_x;0]^T
    gemm_f16<<<dim3(N_COMB/128, M_ROWS/128), 256, F1_SMEM>>>(
        xch, wc16, dx, M_ROWS, N_COMB, DI);
    scan_a<<<dim3(DI/128, CCH, BATCH), 128>>>(A_log, b_dt);
    scan_b<<<dim3(DI/128, BATCH), 128>>>();
    scan_c<<<dim3(DI/128, CCH, BATCH), 128>>>(A_log, Dp, b_dt);
    gemm_fp16<<<dim3(DM/128, M_ROWS/64), 256, T3_SMEM>>>(
        y16, wo16, out, M_ROWS, DM, DI);
}